// round 5
// baseline (speedup 1.0000x reference)
#include <cuda_runtime.h>
#include <math.h>

#define BB   4
#define NN   8192
#define CC   256
#define DD   256
#define LSEG 2048
#define NSEG 28

typedef unsigned long long ull;

// ---------------- packed fp32x2 helpers (sm_100+ PTX) ----------------------
__device__ __forceinline__ void ffma2(ull &d, ull a, ull b) {
    asm("fma.rn.f32x2 %0, %1, %2, %0;" : "+l"(d) : "l"(a), "l"(b));
}
__device__ __forceinline__ void fmul2(ull &d, ull s) {
    asm("mul.rn.f32x2 %0, %0, %1;" : "+l"(d) : "l"(s));
}
__device__ __forceinline__ ull bcast2(float x) {
    ull r; asm("mov.b64 %0, {%1, %1};" : "=l"(r) : "f"(x)); return r;
}
__device__ __forceinline__ float2 unpack2(ull v) {
    float2 r; asm("mov.b64 {%0, %1}, %2;" : "=f"(r.x), "=f"(r.y) : "l"(v)); return r;
}

// ---------------- scratch (__device__ globals; no runtime alloc) ----------
__device__ float g_Q[BB * NN * DD];
__device__ float g_K[BB * NN * DD];
__device__ float g_V[BB * NN * DD];
__device__ float g_O[NSEG * LSEG * DD];
__device__ float g_den[NSEG * LSEG];

// ---------------- Phase 1: QKV projection GEMM ----------------------------
// X[32768,256] @ W[256,256] -> {Q,K,V}[32768,256].  grid=(512,4,3), 256 thr.
// Output columns paired: thread owns cols {2tx+32jp, 2tx+32jp+1}, jp in 0..1.
__global__ __launch_bounds__(256) void qkv_kernel(
    const float* __restrict__ X, const float* __restrict__ Wq,
    const float* __restrict__ Wk, const float* __restrict__ Wv)
{
    const float* W   = (blockIdx.z == 0) ? Wq : (blockIdx.z == 1) ? Wk : Wv;
    float*       Out = (blockIdx.z == 0) ? g_Q : (blockIdx.z == 1) ? g_K : g_V;
    const int m0 = blockIdx.x * 64, n0 = blockIdx.y * 64;

    __shared__ float Xs[64 * 33];
    __shared__ float Ws[32 * 68];

    const int t = threadIdx.x, tx = t & 15, ty = t >> 4;
    ull acc2[4][2];
#pragma unroll
    for (int i = 0; i < 4; i++) { acc2[i][0] = 0ull; acc2[i][1] = 0ull; }

    for (int k0 = 0; k0 < CC; k0 += 32) {
#pragma unroll
        for (int v = 0; v < 2; v++) {            // 64x32 X tile
            int idx = t + v * 256;
            int row = idx >> 3, c4 = (idx & 7) << 2;
            float4 x4 = *(const float4*)(X + (long)(m0 + row) * CC + k0 + c4);
            float* xs = Xs + row * 33 + c4;
            xs[0] = x4.x; xs[1] = x4.y; xs[2] = x4.z; xs[3] = x4.w;
        }
#pragma unroll
        for (int v = 0; v < 2; v++) {            // 32x64 W tile (stride 68, 16B aligned)
            int idx = t + v * 256;
            int row = idx >> 4, c4 = (idx & 15) << 2;
            float4 w4 = *(const float4*)(W + (long)(k0 + row) * DD + n0 + c4);
            *(float4*)(Ws + row * 68 + c4) = w4;
        }
        __syncthreads();
#pragma unroll 8
        for (int kk = 0; kk < 32; kk++) {
            ull a2[4], b2[2];
#pragma unroll
            for (int i = 0; i < 4; i++) a2[i] = bcast2(Xs[(ty + 16 * i) * 33 + kk]);
#pragma unroll
            for (int jp = 0; jp < 2; jp++)
                b2[jp] = *(const ull*)(Ws + kk * 68 + 2 * tx + 32 * jp);
#pragma unroll
            for (int i = 0; i < 4; i++)
#pragma unroll
                for (int jp = 0; jp < 2; jp++) ffma2(acc2[i][jp], a2[i], b2[jp]);
        }
        __syncthreads();
    }
#pragma unroll
    for (int i = 0; i < 4; i++)
#pragma unroll
        for (int jp = 0; jp < 2; jp++) {
            float2 u = unpack2(acc2[i][jp]);
            *(float2*)(Out + (long)(m0 + ty + 16 * i) * DD + n0 + 2 * tx + 32 * jp) =
                make_float2(u.x, u.y);
        }
}

// ---------------- Phase 2: per-segment causal flash attention --------------
__device__ __forceinline__ float rmax16(float v) {
#pragma unroll
    for (int o = 8; o > 0; o >>= 1)
        v = fmaxf(v, __shfl_xor_sync(0xffffffffu, v, o, 16));
    return v;
}
__device__ __forceinline__ float rsum16(float v) {
#pragma unroll
    for (int o = 8; o > 0; o >>= 1)
        v += __shfl_xor_sync(0xffffffffu, v, o, 16);
    return v;
}

#define QS_STRIDE 260                        // 1040B rows: 16B aligned
#define PS_STRIDE 65
#define KS_STRIDE 36                         // 144B rows: 16B aligned
#define PS_OFF    (64 * QS_STRIDE)           // 16640 floats
#define KV_OFF    (PS_OFF + 64 * PS_STRIDE)  // 20800 floats
#define SMEM_FLOATS (KV_OFF + 32 * 256)      // 28992 floats = 115968 B

// grid = (32 q-tiles, 28 segments), 256 threads
__global__ __launch_bounds__(256, 1) void attn_kernel()
{
    extern __shared__ float sm[];
    float* Qs  = sm;
    float* Ps  = sm + PS_OFF;
    float* KVs = sm + KV_OFF;

    const int qt = 31 - (int)blockIdx.x;     // heavy (causal-long) tiles first
    const int s  = blockIdx.y;
    int w, r, base;
    if (s < 16)      { w = 2048; r = 1; base = 0;  }
    else if (s < 24) { w = 4096; r = 2; base = 16; }
    else             { w = 8192; r = 4; base = 24; }
    const int local  = s - base;
    const int seg_id = local >> 2, batch = local & 3;
    const long qkvbase = (long)batch * (NN * DD);
    const int  posbase = seg_id * w;

    const int t = threadIdx.x, tx = t & 15, ty = t >> 4;

    // load 64x256 Q tile, pre-scaled by 1/sqrt(D)=1/16 (exact pow2)
#pragma unroll
    for (int v = 0; v < 16; v++) {
        int idx = t + v * 256;
        int row = idx >> 6, c4 = (idx & 63) << 2;
        long g = qkvbase + (long)(posbase + (qt * 64 + row) * r) * DD + c4;
        float4 q4 = *(const float4*)(g_Q + g);
        q4.x *= 0.0625f; q4.y *= 0.0625f; q4.z *= 0.0625f; q4.w *= 0.0625f;
        *(float4*)(Qs + row * QS_STRIDE + c4) = q4;
    }

    float m_i[4], l_i[4];
    ull o2[4][8];                            // packed output cols {2tx+32cp, +1}
#pragma unroll
    for (int i = 0; i < 4; i++) {
        m_i[i] = -1e30f; l_i[i] = 0.f;
#pragma unroll
        for (int cp = 0; cp < 8; cp++) o2[i][cp] = 0ull;
    }
    __syncthreads();

    for (int kt = 0; kt <= qt; kt++) {
        const long kbase = qkvbase + (long)(posbase + kt * 64 * r) * DD;
        ull sc2[4][4];                       // packed over even/odd k
#pragma unroll
        for (int i = 0; i < 4; i++)
#pragma unroll
            for (int j = 0; j < 4; j++) sc2[i][j] = 0ull;

        // S = Q K^T in 8 k-slabs of 32, k paired (both operands k-contiguous)
        for (int k0 = 0; k0 < DD; k0 += 32) {
#pragma unroll
            for (int v = 0; v < 2; v++) {    // 64x32 K slab, stride 36
                int idx = t + v * 256;
                int row = idx >> 3, c4 = (idx & 7) << 2;
                float4 k4 = *(const float4*)(g_K + kbase + (long)row * r * DD + k0 + c4);
                *(float4*)(KVs + row * KS_STRIDE + c4) = k4;
            }
            __syncthreads();
#pragma unroll
            for (int kk = 0; kk < 32; kk += 4) {
                ulonglong2 a2[4], b2[4];
#pragma unroll
                for (int i = 0; i < 4; i++)
                    a2[i] = *(const ulonglong2*)(Qs + (ty + 16 * i) * QS_STRIDE + k0 + kk);
#pragma unroll
                for (int j = 0; j < 4; j++)
                    b2[j] = *(const ulonglong2*)(KVs + (tx + 16 * j) * KS_STRIDE + kk);
#pragma unroll
                for (int i = 0; i < 4; i++)
#pragma unroll
                    for (int j = 0; j < 4; j++) {
                        ffma2(sc2[i][j], a2[i].x, b2[j].x);
                        ffma2(sc2[i][j], a2[i].y, b2[j].y);
                    }
            }
            __syncthreads();
        }

        float sc[4][4];                      // horizontal reduce of packed pairs
#pragma unroll
        for (int i = 0; i < 4; i++)
#pragma unroll
            for (int j = 0; j < 4; j++) {
                float2 u = unpack2(sc2[i][j]);
                sc[i][j] = u.x + u.y;
            }

        if (kt == qt) {                      // diagonal tile: causal mask
#pragma unroll
            for (int i = 0; i < 4; i++)
#pragma unroll
                for (int j = 0; j < 4; j++)
                    if (tx + 16 * j > ty + 16 * i) sc[i][j] = -1e30f;
        }

        // online softmax update
#pragma unroll
        for (int i = 0; i < 4; i++) {
            float mt = fmaxf(fmaxf(sc[i][0], sc[i][1]), fmaxf(sc[i][2], sc[i][3]));
            mt = rmax16(mt);
            float mnew = fmaxf(m_i[i], mt);
            float scale = __expf(m_i[i] - mnew);
            m_i[i] = mnew;
            float r0 = 0.f;
#pragma unroll
            for (int j = 0; j < 4; j++) {
                float p = __expf(sc[i][j] - mnew);
                Ps[(ty + 16 * i) * PS_STRIDE + tx + 16 * j] = p;
                r0 += p;
            }
            l_i[i] = l_i[i] * scale + rsum16(r0);
            ull s2 = bcast2(scale);
#pragma unroll
            for (int cp = 0; cp < 8; cp++) fmul2(o2[i][cp], s2);
        }
        __syncthreads();                     // Ps visible, KVs reusable

        // O += P @ V, V streamed in two 32x256 slabs; output cols paired
#pragma unroll
        for (int j0 = 0; j0 < 64; j0 += 32) {
#pragma unroll
            for (int v = 0; v < 8; v++) {
                int idx = t + v * 256;
                int row = idx >> 6, c4 = (idx & 63) << 2;
                *(float4*)(KVs + row * 256 + c4) =
                    *(const float4*)(g_V + kbase + (long)(j0 + row) * r * DD + c4);
            }
            __syncthreads();
#pragma unroll 4
            for (int j = 0; j < 32; j++) {
                ull pv2[4];
#pragma unroll
                for (int i = 0; i < 4; i++)
                    pv2[i] = bcast2(Ps[(ty + 16 * i) * PS_STRIDE + j0 + j]);
#pragma unroll
                for (int cp = 0; cp < 8; cp++) {
                    ull vv = *(const ull*)(KVs + j * 256 + 2 * tx + 32 * cp);
#pragma unroll
                    for (int i = 0; i < 4; i++) ffma2(o2[i][cp], pv2[i], vv);
                }
            }
            __syncthreads();
        }
    }

    // epilogue: normalized output + unnormalized denominator
#pragma unroll
    for (int i = 0; i < 4; i++) {
        int row = qt * 64 + ty + 16 * i;
        float inv = 1.0f / l_i[i];
#pragma unroll
        for (int cp = 0; cp < 8; cp++) {
            float2 u = unpack2(o2[i][cp]);
            *(float2*)(g_O + (long)(s * LSEG + row) * DD + 2 * tx + 32 * cp) =
                make_float2(u.x * inv, u.y * inv);
        }
        if (tx == 0) g_den[s * LSEG + row] = l_i[i] * __expf(m_i[i]);
    }
}

// ---------------- Phase 3: combine (gather form of scatter-add) ------------
// grid = 8192 blocks x 256 threads; 4 tokens per block, float4 per thread
__global__ __launch_bounds__(256) void combine_kernel(float* __restrict__ out)
{
    const int token = blockIdx.x * 4 + (threadIdx.x >> 6);
    const int lane  = threadIdx.x & 63;
    const int b = token >> 13, p = token & 8191;

    const int slot0 = (p >> 11) * 4 + b, j0 = p & 2047;
    float d0 = g_den[slot0 * LSEG + j0];
    float sum = d0;
    int slot1 = -1, j1 = 0, slot2 = -1, j2 = 0;
    float d1 = 0.f, d2 = 0.f;
    if ((p & 1) == 0) {
        slot1 = 16 + (p >> 12) * 4 + b; j1 = (p & 4095) >> 1;
        d1 = g_den[slot1 * LSEG + j1]; sum += d1;
    }
    if ((p & 3) == 0) {
        slot2 = 24 + b; j2 = p >> 2;
        d2 = g_den[slot2 * LSEG + j2]; sum += d2;
    }
    const float inv = 1.0f / sum;
    const int c = lane << 2;

    float4 o0 = *(const float4*)(g_O + (slot0 * LSEG + j0) * DD + c);
    float a0 = d0 * inv;
    float4 res;
    res.x = o0.x * a0; res.y = o0.y * a0; res.z = o0.z * a0; res.w = o0.w * a0;
    if (slot1 >= 0) {
        float4 o1 = *(const float4*)(g_O + (slot1 * LSEG + j1) * DD + c);
        float a1 = d1 * inv;
        res.x = fmaf(o1.x, a1, res.x); res.y = fmaf(o1.y, a1, res.y);
        res.z = fmaf(o1.z, a1, res.z); res.w = fmaf(o1.w, a1, res.w);
    }
    if (slot2 >= 0) {
        float4 o2v = *(const float4*)(g_O + (slot2 * LSEG + j2) * DD + c);
        float a2 = d2 * inv;
        res.x = fmaf(o2v.x, a2, res.x); res.y = fmaf(o2v.y, a2, res.y);
        res.z = fmaf(o2v.z, a2, res.z); res.w = fmaf(o2v.w, a2, res.w);
    }
    *(float4*)(out + ((long)b * NN + p) * DD + c) = res;
}

// ---------------- launch ---------------------------------------------------
extern "C" void kernel_launch(void* const* d_in, const int* in_sizes, int n_in,
                              void* d_out, int out_size)
{
    (void)in_sizes; (void)n_in; (void)out_size;
    const float* x  = (const float*)d_in[0];
    const float* Wq = (const float*)d_in[1];
    const float* Wk = (const float*)d_in[2];
    const float* Wv = (const float*)d_in[3];

    cudaFuncSetAttribute(attn_kernel, cudaFuncAttributeMaxDynamicSharedMemorySize,
                         SMEM_FLOATS * (int)sizeof(float));

    qkv_kernel<<<dim3(512, 4, 3), 256>>>(x, Wq, Wk, Wv);
    attn_kernel<<<dim3(32, 28), 256, SMEM_FLOATS * sizeof(float)>>>();
    combine_kernel<<<8192, 256>>>((float*)d_out);
}

// round 7
// speedup vs baseline: 2.4494x; 2.4494x over previous
#include <cuda_runtime.h>
#include <cuda_bf16.h>
#include <stdint.h>
#include <math.h>

#define BB   4
#define NN   8192
#define CC   256
#define DD   256
#define LSEG 2048
#define NSEG 28

typedef unsigned long long ull;

// ---------------- packed fp32x2 helpers (qkv kernel) -----------------------
__device__ __forceinline__ void ffma2(ull &d, ull a, ull b) {
    asm("fma.rn.f32x2 %0, %1, %2, %0;" : "+l"(d) : "l"(a), "l"(b));
}
__device__ __forceinline__ ull bcast2(float x) {
    ull r; asm("mov.b64 %0, {%1, %1};" : "=l"(r) : "f"(x)); return r;
}
__device__ __forceinline__ float2 unpack2(ull v) {
    float2 r; asm("mov.b64 {%0, %1}, %2;" : "=f"(r.x), "=f"(r.y) : "l"(v)); return r;
}

// ---------------- cp.async helpers -----------------------------------------
__device__ __forceinline__ uint32_t smem_to_u32(const void* p) {
    uint32_t a;
    asm("{ .reg .u64 t; cvta.to.shared.u64 t, %1; cvt.u32.u64 %0, t; }"
        : "=r"(a) : "l"(p));
    return a;
}
__device__ __forceinline__ void cp16(uint32_t dst, const void* src) {
    asm volatile("cp.async.cg.shared.global [%0], [%1], 16;" :: "r"(dst), "l"(src) : "memory");
}
#define CP_COMMIT() asm volatile("cp.async.commit_group;" ::: "memory")
#define CP_WAIT1()  asm volatile("cp.async.wait_group 1;" ::: "memory")
#define CP_WAIT0()  asm volatile("cp.async.wait_group 0;" ::: "memory")

// ---------------- ldmatrix / mma.sync (sm_80 baseline, ok on compute_103) --
__device__ __forceinline__ void ldsm4(uint32_t (&d)[4], uint32_t addr) {
    asm volatile("ldmatrix.sync.aligned.m8n8.x4.shared.b16 {%0,%1,%2,%3}, [%4];"
        : "=r"(d[0]), "=r"(d[1]), "=r"(d[2]), "=r"(d[3]) : "r"(addr));
}
__device__ __forceinline__ void ldsm2(uint32_t (&d)[2], uint32_t addr) {
    asm volatile("ldmatrix.sync.aligned.m8n8.x2.shared.b16 {%0,%1}, [%2];"
        : "=r"(d[0]), "=r"(d[1]) : "r"(addr));
}
__device__ __forceinline__ void mma_bf16(float (&c)[4], const uint32_t (&a)[4],
                                         const uint32_t (&b)[2]) {
    asm volatile("mma.sync.aligned.m16n8k16.row.col.f32.bf16.bf16.f32 "
        "{%0,%1,%2,%3}, {%4,%5,%6,%7}, {%8,%9}, {%0,%1,%2,%3};"
        : "+f"(c[0]), "+f"(c[1]), "+f"(c[2]), "+f"(c[3])
        : "r"(a[0]), "r"(a[1]), "r"(a[2]), "r"(a[3]), "r"(b[0]), "r"(b[1]));
}

// ---------------- scratch ---------------------------------------------------
__device__ __nv_bfloat16 g_Qh[BB * NN * DD];
__device__ __nv_bfloat16 g_Ql[BB * NN * DD];
__device__ __nv_bfloat16 g_Kh[BB * NN * DD];
__device__ __nv_bfloat16 g_Kl[BB * NN * DD];
__device__ float         g_V [BB * NN * DD];
__device__ __nv_bfloat16 g_Vth[NSEG * DD * LSEG];   // per-slot V^T, hi
__device__ __nv_bfloat16 g_Vtl[NSEG * DD * LSEG];   // per-slot V^T, lo
__device__ float g_O[NSEG * LSEG * DD];
__device__ float g_den[NSEG * LSEG];

__device__ __forceinline__ void slot_decode(int s, int& batch, int& posbase, int& r) {
    int w, base;
    if (s < 16)      { w = 2048; r = 1; base = 0;  }
    else if (s < 24) { w = 4096; r = 2; base = 16; }
    else             { w = 8192; r = 4; base = 24; }
    int local = s - base;
    batch = local & 3;
    posbase = (local >> 2) * w;
}

// ================= Phase 1: QKV projection (SIMT fp32) ======================
__global__ __launch_bounds__(256) void qkv_kernel(
    const float* __restrict__ X, const float* __restrict__ Wq,
    const float* __restrict__ Wk, const float* __restrict__ Wv)
{
    const int z = blockIdx.z;
    const float* W = (z == 0) ? Wq : (z == 1) ? Wk : Wv;
    const int m0 = blockIdx.x * 64, n0 = blockIdx.y * 64;

    __shared__ float Xs[64 * 33];
    __shared__ float Ws[32 * 68];

    const int t = threadIdx.x, tx = t & 15, ty = t >> 4;
    ull acc2[4][2];
#pragma unroll
    for (int i = 0; i < 4; i++) { acc2[i][0] = 0ull; acc2[i][1] = 0ull; }

    for (int k0 = 0; k0 < CC; k0 += 32) {
#pragma unroll
        for (int v = 0; v < 2; v++) {
            int idx = t + v * 256;
            int row = idx >> 3, c4 = (idx & 7) << 2;
            float4 x4 = *(const float4*)(X + (long)(m0 + row) * CC + k0 + c4);
            float* xs = Xs + row * 33 + c4;
            xs[0] = x4.x; xs[1] = x4.y; xs[2] = x4.z; xs[3] = x4.w;
        }
#pragma unroll
        for (int v = 0; v < 2; v++) {
            int idx = t + v * 256;
            int row = idx >> 4, c4 = (idx & 15) << 2;
            *(float4*)(Ws + row * 68 + c4) =
                *(const float4*)(W + (long)(k0 + row) * DD + n0 + c4);
        }
        __syncthreads();
#pragma unroll 8
        for (int kk = 0; kk < 32; kk++) {
            ull a2[4], b2[2];
#pragma unroll
            for (int i = 0; i < 4; i++) a2[i] = bcast2(Xs[(ty + 16 * i) * 33 + kk]);
#pragma unroll
            for (int jp = 0; jp < 2; jp++)
                b2[jp] = *(const ull*)(Ws + kk * 68 + 2 * tx + 32 * jp);
#pragma unroll
            for (int i = 0; i < 4; i++)
#pragma unroll
                for (int jp = 0; jp < 2; jp++) ffma2(acc2[i][jp], a2[i], b2[jp]);
        }
        __syncthreads();
    }
#pragma unroll
    for (int i = 0; i < 4; i++)
#pragma unroll
        for (int jp = 0; jp < 2; jp++) {
            float2 u = unpack2(acc2[i][jp]);
            long off = (long)(m0 + ty + 16 * i) * DD + n0 + 2 * tx + 32 * jp;
            if (z == 2) {
                *(float2*)(g_V + off) = make_float2(u.x, u.y);
            } else {
                float v0 = u.x, v1 = u.y;
                if (z == 0) { v0 *= 0.0625f; v1 *= 0.0625f; }
                __nv_bfloat162 h2 = __floats2bfloat162_rn(v0, v1);
                float r0 = v0 - __bfloat162float(h2.x);
                float r1 = v1 - __bfloat162float(h2.y);
                __nv_bfloat162 l2 = __floats2bfloat162_rn(r0, r1);
                if (z == 0) {
                    *(__nv_bfloat162*)(g_Qh + off) = h2;
                    *(__nv_bfloat162*)(g_Ql + off) = l2;
                } else {
                    *(__nv_bfloat162*)(g_Kh + off) = h2;
                    *(__nv_bfloat162*)(g_Kl + off) = l2;
                }
            }
        }
}

// ================= Phase 1b: per-slot V^T gather+split ======================
__global__ __launch_bounds__(256) void transpose_v_kernel()
{
    __shared__ float T[32][36];
    const int s = blockIdx.z, jt = blockIdx.x, dt = blockIdx.y;
    int batch, posbase, r;
    slot_decode(s, batch, posbase, r);

    const int t = threadIdx.x;
    {
        int jl = t >> 3, dq = (t & 7) << 2;
        int pos = posbase + (jt * 32 + jl) * r;
        float4 v = *(const float4*)(g_V + ((long)batch * NN + pos) * DD + dt * 32 + dq);
        T[jl][dq] = v.x; T[jl][dq + 1] = v.y; T[jl][dq + 2] = v.z; T[jl][dq + 3] = v.w;
    }
    __syncthreads();
    {
        int dl = t >> 3, jq = (t & 7) << 2;
        float v0 = T[jq][dl], v1 = T[jq + 1][dl], v2 = T[jq + 2][dl], v3 = T[jq + 3][dl];
        __nv_bfloat162 h0 = __floats2bfloat162_rn(v0, v1);
        __nv_bfloat162 h1 = __floats2bfloat162_rn(v2, v3);
        __nv_bfloat162 l0 = __floats2bfloat162_rn(v0 - __bfloat162float(h0.x),
                                                  v1 - __bfloat162float(h0.y));
        __nv_bfloat162 l1 = __floats2bfloat162_rn(v2 - __bfloat162float(h1.x),
                                                  v3 - __bfloat162float(h1.y));
        long off = ((long)s * DD + dt * 32 + dl) * LSEG + jt * 32 + jq;
        *(__nv_bfloat162*)(g_Vth + off) = h0;
        *(__nv_bfloat162*)(g_Vth + off + 2) = h1;
        *(__nv_bfloat162*)(g_Vtl + off) = l0;
        *(__nv_bfloat162*)(g_Vtl + off + 2) = l1;
    }
}

// ================= Phase 2: mma.sync bf16-split causal attention ============
// grid=(32 q-tiles of 64, 28 slots), 256 threads (8 warps), 1 CTA/SM.
// smem bytes: Qh 0 | Ql 32K | Kh 64K | Kl 96K | Vh 128K | Vl 160K
//             Ph 192K | Pl 200K | lsum 208K  (rows XOR-swizzled by 16B chunk)
#define OQH 0
#define OQL 32768
#define OKH 65536
#define OKL 98304
#define OVH 131072
#define OVL 163840
#define OPH 196608
#define OPL 204800
#define OLS 212992
#define SM_TOTAL (OLS + 512)

__device__ __forceinline__ uint32_t swz512(uint32_t base, int row, int c16) {
    return base + row * 512 + ((uint32_t)(c16 ^ (row & 7)) << 4);
}
__device__ __forceinline__ uint32_t swz128(uint32_t base, int row, int c16) {
    return base + row * 128 + ((uint32_t)(c16 ^ (row & 7)) << 4);
}
// A-fragment address (ldmatrix x4), rows r0.., k-step ks (16 elems)
__device__ __forceinline__ uint32_t aAddr(uint32_t base, int rowbytes, int r0,
                                          int ks, int lane) {
    int row = r0 + (lane & 7) + ((lane & 8) ? 8 : 0);
    int c16 = ks * 2 + (lane >> 4);
    return base + row * rowbytes + ((uint32_t)(c16 ^ (row & 7)) << 4);
}
// B-fragment address (ldmatrix x2), rows n0..n0+7, k-step ks
__device__ __forceinline__ uint32_t bAddr(uint32_t base, int rowbytes, int n0,
                                          int ks, int lane) {
    int l = lane & 15;
    int row = n0 + (l & 7);
    int c16 = ks * 2 + (l >> 3);
    return base + row * rowbytes + ((uint32_t)(c16 ^ (row & 7)) << 4);
}

__global__ __launch_bounds__(256, 1) void attn_kernel()
{
    extern __shared__ char smem[];
    const uint32_t sb = smem_to_u32(smem);
    float* lsum2 = (float*)(smem + OLS);         // [2][64]

    const int t = threadIdx.x, lane = t & 31, wid = t >> 5;
    const int qt = 31 - (int)blockIdx.x;          // heavy tiles first
    const int s  = blockIdx.y;
    int batch, posbase, r;
    slot_decode(s, batch, posbase, r);
    const long qkvoff = (long)batch * (NN * DD);

    // ---- Q tile (64 x 256, hi/lo) via cp.async ---------------------------
    {
        const __nv_bfloat16* gq[2] = { g_Qh + qkvoff, g_Ql + qkvoff };
#pragma unroll
        for (int sp = 0; sp < 2; sp++)
#pragma unroll
            for (int i = 0; i < 8; i++) {
                int e = t + i * 256;              // 0..2047
                int row = e >> 5, c16 = e & 31;
                cp16(swz512(sb + (sp ? OQL : OQH), row, c16),
                     gq[sp] + ((long)(posbase + (qt * 64 + row) * r)) * DD + c16 * 8);
            }
        CP_COMMIT();
    }

    const int g = lane >> 2, cpair = 2 * (lane & 3);
    const int wq = wid & 3, wk = wid >> 2;        // S-phase decomposition
    float accd[4][4][4];                          // PV accum: [mt][nt][4]
#pragma unroll
    for (int mt = 0; mt < 4; mt++)
#pragma unroll
        for (int nt = 0; nt < 4; nt++)
#pragma unroll
            for (int c = 0; c < 4; c++) accd[mt][nt][c] = 0.f;
    float rs0 = 0.f, rs1 = 0.f;                   // row-sum partials

    for (int kt = 0; kt <= qt; kt++) {
        __syncthreads();                          // prev PV done (V, P reusable)
        // ---- issue K chunk (64 x 256 hi/lo) ------------------------------
        {
            const __nv_bfloat16* gk[2] = { g_Kh + qkvoff, g_Kl + qkvoff };
#pragma unroll
            for (int sp = 0; sp < 2; sp++)
#pragma unroll
                for (int i = 0; i < 8; i++) {
                    int e = t + i * 256;
                    int key = e >> 5, c16 = e & 31;
                    cp16(swz512(sb + (sp ? OKL : OKH), key, c16),
                         gk[sp] + ((long)(posbase + (kt * 64 + key) * r)) * DD + c16 * 8);
                }
            CP_COMMIT();
        }
        // ---- issue V^T chunk (256 x 64 hi/lo) ----------------------------
        {
            const __nv_bfloat16* gv[2] = { g_Vth + (long)s * DD * LSEG,
                                           g_Vtl + (long)s * DD * LSEG };
#pragma unroll
            for (int sp = 0; sp < 2; sp++)
#pragma unroll
                for (int i = 0; i < 8; i++) {
                    int e = t + i * 256;
                    int d = e >> 3, c16 = e & 7;
                    cp16(swz128(sb + (sp ? OVL : OVH), d, c16),
                         gv[sp] + (long)d * LSEG + kt * 64 + c16 * 8);
                }
            CP_COMMIT();
        }
        CP_WAIT1();                               // K (and Q) ready; V in flight
        __syncthreads();

        // ---- S = Q K^T: warp computes 16q x 32k, 3 split terms -----------
        float sacc[4][4];
#pragma unroll
        for (int nt = 0; nt < 4; nt++)
#pragma unroll
            for (int c = 0; c < 4; c++) sacc[nt][c] = 0.f;
#pragma unroll 4
        for (int ks = 0; ks < 16; ks++) {
            uint32_t ah[4], al[4];
            ldsm4(ah, aAddr(sb + OQH, 512, wq * 16, ks, lane));
            ldsm4(al, aAddr(sb + OQL, 512, wq * 16, ks, lane));
#pragma unroll
            for (int nt = 0; nt < 4; nt++) {
                uint32_t bh[2], bl[2];
                ldsm2(bh, bAddr(sb + OKH, 512, wk * 32 + nt * 8, ks, lane));
                ldsm2(bl, bAddr(sb + OKL, 512, wk * 32 + nt * 8, ks, lane));
                mma_bf16(sacc[nt], ah, bh);
                mma_bf16(sacc[nt], ah, bl);
                mma_bf16(sacc[nt], al, bh);
            }
        }

        // ---- softmax: mask, exp, row-sum, pack P hi/lo to smem ------------
        const int prow0 = wq * 16 + g, prow1 = prow0 + 8;
        const int qrow0 = qt * 64 + prow0, qrow1 = qt * 64 + prow1;
#pragma unroll
        for (int nt = 0; nt < 4; nt++) {
            int kcol = wk * 32 + nt * 8 + cpair;
            int kg = kt * 64 + kcol;
            float p00 = (kg     <= qrow0) ? __expf(sacc[nt][0]) : 0.f;
            float p01 = (kg + 1 <= qrow0) ? __expf(sacc[nt][1]) : 0.f;
            float p10 = (kg     <= qrow1) ? __expf(sacc[nt][2]) : 0.f;
            float p11 = (kg + 1 <= qrow1) ? __expf(sacc[nt][3]) : 0.f;
            rs0 += p00 + p01;
            rs1 += p10 + p11;
            __nv_bfloat162 h0 = __floats2bfloat162_rn(p00, p01);
            __nv_bfloat162 l0 = __floats2bfloat162_rn(p00 - __bfloat162float(h0.x),
                                                      p01 - __bfloat162float(h0.y));
            __nv_bfloat162 h1 = __floats2bfloat162_rn(p10, p11);
            __nv_bfloat162 l1 = __floats2bfloat162_rn(p10 - __bfloat162float(h1.x),
                                                      p11 - __bfloat162float(h1.y));
            uint32_t ob0 = prow0 * 128 + ((uint32_t)((kcol >> 3) ^ (prow0 & 7)) << 4)
                         + (kcol & 7) * 2;
            uint32_t ob1 = prow1 * 128 + ((uint32_t)((kcol >> 3) ^ (prow1 & 7)) << 4)
                         + (kcol & 7) * 2;
            *(__nv_bfloat162*)(smem + OPH + ob0) = h0;
            *(__nv_bfloat162*)(smem + OPL + ob0) = l0;
            *(__nv_bfloat162*)(smem + OPH + ob1) = h1;
            *(__nv_bfloat162*)(smem + OPL + ob1) = l1;
        }
        CP_WAIT0();                               // V ready
        __syncthreads();                          // P + V visible to all

        // ---- D += P V: warp owns d-cols [wid*32, wid*32+32), all 64 q ----
        const int n0 = wid * 32;
#pragma unroll
        for (int ks = 0; ks < 4; ks++) {
            uint32_t bh[4][2], bl[4][2];
#pragma unroll
            for (int nt = 0; nt < 4; nt++) {
                ldsm2(bh[nt], bAddr(sb + OVH, 128, n0 + nt * 8, ks, lane));
                ldsm2(bl[nt], bAddr(sb + OVL, 128, n0 + nt * 8, ks, lane));
            }
#pragma unroll
            for (int mt = 0; mt < 4; mt++) {
                uint32_t ah[4], al[4];
                ldsm4(ah, aAddr(sb + OPH, 128, mt * 16, ks, lane));
                ldsm4(al, aAddr(sb + OPL, 128, mt * 16, ks, lane));
#pragma unroll
                for (int nt = 0; nt < 4; nt++) {
                    mma_bf16(accd[mt][nt], ah, bh[nt]);
                    mma_bf16(accd[mt][nt], ah, bl[nt]);
                    mma_bf16(accd[mt][nt], al, bh[nt]);
                }
            }
        }
    }

    // ---- epilogue ---------------------------------------------------------
    rs0 += __shfl_xor_sync(0xffffffffu, rs0, 1);
    rs0 += __shfl_xor_sync(0xffffffffu, rs0, 2);
    rs1 += __shfl_xor_sync(0xffffffffu, rs1, 1);
    rs1 += __shfl_xor_sync(0xffffffffu, rs1, 2);
    if ((lane & 3) == 0) {
        lsum2[wk * 64 + wq * 16 + g]     = rs0;
        lsum2[wk * 64 + wq * 16 + g + 8] = rs1;
    }
    __syncthreads();

#pragma unroll
    for (int mt = 0; mt < 4; mt++) {
        int lr0 = mt * 16 + g, lr1 = lr0 + 8;
        float inv0 = 1.0f / (lsum2[lr0] + lsum2[64 + lr0]);
        float inv1 = 1.0f / (lsum2[lr1] + lsum2[64 + lr1]);
        long ro0 = (long)(s * LSEG + qt * 64 + lr0) * DD;
        long ro1 = (long)(s * LSEG + qt * 64 + lr1) * DD;
#pragma unroll
        for (int nt = 0; nt < 4; nt++) {
            int col = wid * 32 + nt * 8 + cpair;
            *(float2*)(g_O + ro0 + col) =
                make_float2(accd[mt][nt][0] * inv0, accd[mt][nt][1] * inv0);
            *(float2*)(g_O + ro1 + col) =
                make_float2(accd[mt][nt][2] * inv1, accd[mt][nt][3] * inv1);
        }
    }
    if (t < 64)
        g_den[s * LSEG + qt * 64 + t] = lsum2[t] + lsum2[64 + t];
}

// ================= Phase 3: combine (gather) ================================
__global__ __launch_bounds__(256) void combine_kernel(float* __restrict__ out)
{
    const int token = blockIdx.x * 4 + (threadIdx.x >> 6);
    const int lane  = threadIdx.x & 63;
    const int b = token >> 13, p = token & 8191;

    const int slot0 = (p >> 11) * 4 + b, j0 = p & 2047;
    float d0 = g_den[slot0 * LSEG + j0];
    float sum = d0;
    int slot1 = -1, j1 = 0, slot2 = -1, j2 = 0;
    float d1 = 0.f, d2 = 0.f;
    if ((p & 1) == 0) {
        slot1 = 16 + (p >> 12) * 4 + b; j1 = (p & 4095) >> 1;
        d1 = g_den[slot1 * LSEG + j1]; sum += d1;
    }
    if ((p & 3) == 0) {
        slot2 = 24 + b; j2 = p >> 2;
        d2 = g_den[slot2 * LSEG + j2]; sum += d2;
    }
    const float inv = 1.0f / sum;
    const int c = lane << 2;

    float4 o0 = *(const float4*)(g_O + ((long)slot0 * LSEG + j0) * DD + c);
    float a0 = d0 * inv;
    float4 res;
    res.x = o0.x * a0; res.y = o0.y * a0; res.z = o0.z * a0; res.w = o0.w * a0;
    if (slot1 >= 0) {
        float4 o1 = *(const float4*)(g_O + ((long)slot1 * LSEG + j1) * DD + c);
        float a1 = d1 * inv;
        res.x = fmaf(o1.x, a1, res.x); res.y = fmaf(o1.y, a1, res.y);
        res.z = fmaf(o1.z, a1, res.z); res.w = fmaf(o1.w, a1, res.w);
    }
    if (slot2 >= 0) {
        float4 o2v = *(const float4*)(g_O + ((long)slot2 * LSEG + j2) * DD + c);
        float a2 = d2 * inv;
        res.x = fmaf(o2v.x, a2, res.x); res.y = fmaf(o2v.y, a2, res.y);
        res.z = fmaf(o2v.z, a2, res.z); res.w = fmaf(o2v.w, a2, res.w);
    }
    *(float4*)(out + ((long)b * NN + p) * DD + c) = res;
}

// ================= launch ====================================================
extern "C" void kernel_launch(void* const* d_in, const int* in_sizes, int n_in,
                              void* d_out, int out_size)
{
    (void)in_sizes; (void)n_in; (void)out_size;
    const float* x  = (const float*)d_in[0];
    const float* Wq = (const float*)d_in[1];
    const float* Wk = (const float*)d_in[2];
    const float* Wv = (const float*)d_in[3];

    cudaFuncSetAttribute(attn_kernel, cudaFuncAttributeMaxDynamicSharedMemorySize,
                         SM_TOTAL);

    qkv_kernel<<<dim3(512, 4, 3), 256>>>(x, Wq, Wk, Wv);
    transpose_v_kernel<<<dim3(64, 8, 28), 256>>>();
    attn_kernel<<<dim3(32, 28), 256, SM_TOTAL>>>();
    combine_kernel<<<8192, 256>>>((float*)d_out);
}

// round 8
// speedup vs baseline: 3.3583x; 1.3711x over previous
#include <cuda_runtime.h>
#include <cuda_bf16.h>
#include <stdint.h>
#include <math.h>

#define BB   4
#define NN   8192
#define CC   256
#define DD   256
#define LSEG 2048
#define NSEG 28

// ---------------- cp.async helpers -----------------------------------------
__device__ __forceinline__ uint32_t smem_to_u32(const void* p) {
    uint32_t a;
    asm("{ .reg .u64 t; cvta.to.shared.u64 t, %1; cvt.u32.u64 %0, t; }"
        : "=r"(a) : "l"(p));
    return a;
}
__device__ __forceinline__ void cp16(uint32_t dst, const void* src) {
    asm volatile("cp.async.cg.shared.global [%0], [%1], 16;" :: "r"(dst), "l"(src) : "memory");
}
#define CP_COMMIT() asm volatile("cp.async.commit_group;" ::: "memory")
#define CP_WAIT1()  asm volatile("cp.async.wait_group 1;" ::: "memory")
#define CP_WAIT0()  asm volatile("cp.async.wait_group 0;" ::: "memory")

// ---------------- ldmatrix / mma.sync ---------------------------------------
__device__ __forceinline__ void ldsm4(uint32_t (&d)[4], uint32_t addr) {
    asm volatile("ldmatrix.sync.aligned.m8n8.x4.shared.b16 {%0,%1,%2,%3}, [%4];"
        : "=r"(d[0]), "=r"(d[1]), "=r"(d[2]), "=r"(d[3]) : "r"(addr));
}
__device__ __forceinline__ void mma_bf16(float (&c)[4], const uint32_t (&a)[4],
                                         uint32_t b0, uint32_t b1) {
    asm volatile("mma.sync.aligned.m16n8k16.row.col.f32.bf16.bf16.f32 "
        "{%0,%1,%2,%3}, {%4,%5,%6,%7}, {%8,%9}, {%0,%1,%2,%3};"
        : "+f"(c[0]), "+f"(c[1]), "+f"(c[2]), "+f"(c[3])
        : "r"(a[0]), "r"(a[1]), "r"(a[2]), "r"(a[3]), "r"(b0), "r"(b1));
}

// A-fragment address (ldmatrix x4): 16 rows starting r0, k-step ks (16 elems)
__device__ __forceinline__ uint32_t aAddr(uint32_t base, int rowbytes, int r0,
                                          int ks, int lane) {
    int row = r0 + (lane & 7) + ((lane & 8) ? 8 : 0);
    int c16 = ks * 2 + (lane >> 4);
    return base + row * rowbytes + ((uint32_t)(c16 ^ (row & 7)) << 4);
}
// B-fragment address (ldmatrix x4): 8 rows at n0, TWO k-steps (pair kp)
__device__ __forceinline__ uint32_t b4Addr(uint32_t base, int rowbytes, int n0,
                                           int kp, int lane) {
    int row = n0 + (lane & 7);
    int c16 = kp * 4 + (lane >> 3);
    return base + row * rowbytes + ((uint32_t)(c16 ^ (row & 7)) << 4);
}
__device__ __forceinline__ uint32_t swz512(uint32_t base, int row, int c16) {
    return base + row * 512 + ((uint32_t)(c16 ^ (row & 7)) << 4);
}
__device__ __forceinline__ uint32_t swz128(uint32_t base, int row, int c16) {
    return base + row * 128 + ((uint32_t)(c16 ^ (row & 7)) << 4);
}

// ---------------- scratch ---------------------------------------------------
__device__ __nv_bfloat16 g_Xh[BB * NN * CC];
__device__ __nv_bfloat16 g_Xl[BB * NN * CC];
__device__ __nv_bfloat16 g_Wht[3 * CC * DD];        // [z][n][k] transposed
__device__ __nv_bfloat16 g_Wlt[3 * CC * DD];
__device__ __nv_bfloat16 g_Qh[BB * NN * DD];
__device__ __nv_bfloat16 g_Ql[BB * NN * DD];
__device__ __nv_bfloat16 g_Kh[BB * NN * DD];
__device__ __nv_bfloat16 g_Kl[BB * NN * DD];
__device__ float         g_V [BB * NN * DD];
__device__ __nv_bfloat16 g_Vth[NSEG * DD * LSEG];
__device__ __nv_bfloat16 g_Vtl[NSEG * DD * LSEG];
__device__ float g_O[NSEG * LSEG * DD];
__device__ float g_den[NSEG * LSEG];

__device__ __forceinline__ void slot_decode(int s, int& batch, int& posbase, int& r) {
    int w, base;
    if (s < 16)      { w = 2048; r = 1; base = 0;  }
    else if (s < 24) { w = 4096; r = 2; base = 16; }
    else             { w = 8192; r = 4; base = 24; }
    int local = s - base;
    batch = local & 3;
    posbase = (local >> 2) * w;
}

// ================= Phase 0a: split X into bf16 hi/lo ========================
__global__ __launch_bounds__(256) void split_x_kernel(const float* __restrict__ X)
{
    long e = (long)blockIdx.x * 1024 + threadIdx.x * 4;
    float4 v = *(const float4*)(X + e);
    __nv_bfloat162 h0 = __floats2bfloat162_rn(v.x, v.y);
    __nv_bfloat162 h1 = __floats2bfloat162_rn(v.z, v.w);
    __nv_bfloat162 l0 = __floats2bfloat162_rn(v.x - __bfloat162float(h0.x),
                                              v.y - __bfloat162float(h0.y));
    __nv_bfloat162 l1 = __floats2bfloat162_rn(v.z - __bfloat162float(h1.x),
                                              v.w - __bfloat162float(h1.y));
    *(__nv_bfloat162*)(g_Xh + e) = h0; *(__nv_bfloat162*)(g_Xh + e + 2) = h1;
    *(__nv_bfloat162*)(g_Xl + e) = l0; *(__nv_bfloat162*)(g_Xl + e + 2) = l1;
}

// ================= Phase 0b: transpose+split W ==============================
// grid (8 k-tiles, 8 n-tiles, 3 z), 256 thr; Wq pre-scaled by 1/16.
__global__ __launch_bounds__(256) void split_w_kernel(
    const float* __restrict__ Wq, const float* __restrict__ Wk,
    const float* __restrict__ Wv)
{
    __shared__ float T[32][33];
    const int z = blockIdx.z;
    const float* W = (z == 0) ? Wq : (z == 1) ? Wk : Wv;
    const int k0 = blockIdx.x * 32, n0 = blockIdx.y * 32;
    const int t = threadIdx.x;
    {
        int kk = t >> 3, n4 = (t & 7) << 2;
        float4 v = *(const float4*)(W + (long)(k0 + kk) * DD + n0 + n4);
        T[kk][n4] = v.x; T[kk][n4 + 1] = v.y; T[kk][n4 + 2] = v.z; T[kk][n4 + 3] = v.w;
    }
    __syncthreads();
    {
        int nn = t >> 3, k4 = (t & 7) << 2;
        float sc = (z == 0) ? 0.0625f : 1.0f;
        float v0 = T[k4][nn] * sc, v1 = T[k4 + 1][nn] * sc;
        float v2 = T[k4 + 2][nn] * sc, v3 = T[k4 + 3][nn] * sc;
        __nv_bfloat162 h0 = __floats2bfloat162_rn(v0, v1);
        __nv_bfloat162 h1 = __floats2bfloat162_rn(v2, v3);
        __nv_bfloat162 l0 = __floats2bfloat162_rn(v0 - __bfloat162float(h0.x),
                                                  v1 - __bfloat162float(h0.y));
        __nv_bfloat162 l1 = __floats2bfloat162_rn(v2 - __bfloat162float(h1.x),
                                                  v3 - __bfloat162float(h1.y));
        long off = (long)z * (CC * DD) + (long)(n0 + nn) * CC + k0 + k4;
        *(__nv_bfloat162*)(g_Wht + off) = h0; *(__nv_bfloat162*)(g_Wht + off + 2) = h1;
        *(__nv_bfloat162*)(g_Wlt + off) = l0; *(__nv_bfloat162*)(g_Wlt + off + 2) = l1;
    }
}

// ================= Phase 1: QKV projection via mma.sync =====================
// grid=(256 m-tiles of 128, 2 n-tiles of 128, 3 z), 256 thr (8 warps).
// smem: Xh[2][128][64] | Xl | Wh[2][128n][64k] | Wl   (double buffered slabs)
#define GX_H 0
#define GX_L 32768
#define GW_H 65536
#define GW_L 98304
#define QKV_SMEM 131072

__global__ __launch_bounds__(256, 1) void qkv_mma_kernel()
{
    extern __shared__ char smem[];
    const uint32_t sb = smem_to_u32(smem);
    const int t = threadIdx.x, lane = t & 31, wid = t >> 5;
    const int m0 = blockIdx.x * 128, n0 = blockIdx.y * 128, z = blockIdx.z;
    const __nv_bfloat16* Wh = g_Wht + (long)z * (CC * DD);
    const __nv_bfloat16* Wl = g_Wlt + (long)z * (CC * DD);

    auto loadslab = [&](int s, int buf) {
        int k0 = s * 64;
        uint32_t bo = (uint32_t)buf * 16384;
#pragma unroll
        for (int i = 0; i < 4; i++) {
            int e = t + i * 256;                  // 0..1023
            int row = e >> 3, c16 = e & 7;
            long xs = (long)(m0 + row) * CC + k0 + c16 * 8;
            cp16(swz128(sb + GX_H + bo, row, c16), g_Xh + xs);
            cp16(swz128(sb + GX_L + bo, row, c16), g_Xl + xs);
            long ws = (long)(n0 + row) * CC + k0 + c16 * 8;
            cp16(swz128(sb + GW_H + bo, row, c16), Wh + ws);
            cp16(swz128(sb + GW_L + bo, row, c16), Wl + ws);
        }
    };

    float acc[16][4];
#pragma unroll
    for (int nt = 0; nt < 16; nt++)
#pragma unroll
        for (int c = 0; c < 4; c++) acc[nt][c] = 0.f;

    loadslab(0, 0); CP_COMMIT();
    for (int s = 0; s < 4; s++) {
        if (s < 3) { loadslab(s + 1, (s + 1) & 1); CP_COMMIT(); CP_WAIT1(); }
        else CP_WAIT0();
        __syncthreads();
        uint32_t bo = (uint32_t)(s & 1) * 16384;
#pragma unroll
        for (int kp = 0; kp < 2; kp++) {
            uint32_t ah0[4], ah1[4], al0[4], al1[4];
            ldsm4(ah0, aAddr(sb + GX_H + bo, 128, wid * 16, 2 * kp,     lane));
            ldsm4(ah1, aAddr(sb + GX_H + bo, 128, wid * 16, 2 * kp + 1, lane));
            ldsm4(al0, aAddr(sb + GX_L + bo, 128, wid * 16, 2 * kp,     lane));
            ldsm4(al1, aAddr(sb + GX_L + bo, 128, wid * 16, 2 * kp + 1, lane));
#pragma unroll
            for (int nt = 0; nt < 16; nt++) {
                uint32_t bh[4], bl[4];
                ldsm4(bh, b4Addr(sb + GW_H + bo, 128, nt * 8, kp, lane));
                ldsm4(bl, b4Addr(sb + GW_L + bo, 128, nt * 8, kp, lane));
                mma_bf16(acc[nt], ah0, bh[0], bh[1]);
                mma_bf16(acc[nt], ah0, bl[0], bl[1]);
                mma_bf16(acc[nt], al0, bh[0], bh[1]);
                mma_bf16(acc[nt], ah1, bh[2], bh[3]);
                mma_bf16(acc[nt], ah1, bl[2], bl[3]);
                mma_bf16(acc[nt], al1, bh[2], bh[3]);
            }
        }
        __syncthreads();
    }

    // epilogue
    const int g = lane >> 2, cpair = 2 * (lane & 3);
#pragma unroll
    for (int nt = 0; nt < 16; nt++) {
        long r0 = (long)(m0 + wid * 16 + g) * DD + n0 + nt * 8 + cpair;
        long r1 = r0 + 8 * DD;
        if (z == 2) {
            *(float2*)(g_V + r0) = make_float2(acc[nt][0], acc[nt][1]);
            *(float2*)(g_V + r1) = make_float2(acc[nt][2], acc[nt][3]);
        } else {
            __nv_bfloat162 h0 = __floats2bfloat162_rn(acc[nt][0], acc[nt][1]);
            __nv_bfloat162 l0 = __floats2bfloat162_rn(acc[nt][0] - __bfloat162float(h0.x),
                                                      acc[nt][1] - __bfloat162float(h0.y));
            __nv_bfloat162 h1 = __floats2bfloat162_rn(acc[nt][2], acc[nt][3]);
            __nv_bfloat162 l1 = __floats2bfloat162_rn(acc[nt][2] - __bfloat162float(h1.x),
                                                      acc[nt][3] - __bfloat162float(h1.y));
            if (z == 0) {
                *(__nv_bfloat162*)(g_Qh + r0) = h0; *(__nv_bfloat162*)(g_Ql + r0) = l0;
                *(__nv_bfloat162*)(g_Qh + r1) = h1; *(__nv_bfloat162*)(g_Ql + r1) = l1;
            } else {
                *(__nv_bfloat162*)(g_Kh + r0) = h0; *(__nv_bfloat162*)(g_Kl + r0) = l0;
                *(__nv_bfloat162*)(g_Kh + r1) = h1; *(__nv_bfloat162*)(g_Kl + r1) = l1;
            }
        }
    }
}

// ================= Phase 1b: per-slot V^T gather+split ======================
__global__ __launch_bounds__(256) void transpose_v_kernel()
{
    __shared__ float T[32][36];
    const int s = blockIdx.z, jt = blockIdx.x, dt = blockIdx.y;
    int batch, posbase, r;
    slot_decode(s, batch, posbase, r);

    const int t = threadIdx.x;
    {
        int jl = t >> 3, dq = (t & 7) << 2;
        int pos = posbase + (jt * 32 + jl) * r;
        float4 v = *(const float4*)(g_V + ((long)batch * NN + pos) * DD + dt * 32 + dq);
        T[jl][dq] = v.x; T[jl][dq + 1] = v.y; T[jl][dq + 2] = v.z; T[jl][dq + 3] = v.w;
    }
    __syncthreads();
    {
        int dl = t >> 3, jq = (t & 7) << 2;
        float v0 = T[jq][dl], v1 = T[jq + 1][dl], v2 = T[jq + 2][dl], v3 = T[jq + 3][dl];
        __nv_bfloat162 h0 = __floats2bfloat162_rn(v0, v1);
        __nv_bfloat162 h1 = __floats2bfloat162_rn(v2, v3);
        __nv_bfloat162 l0 = __floats2bfloat162_rn(v0 - __bfloat162float(h0.x),
                                                  v1 - __bfloat162float(h0.y));
        __nv_bfloat162 l1 = __floats2bfloat162_rn(v2 - __bfloat162float(h1.x),
                                                  v3 - __bfloat162float(h1.y));
        long off = ((long)s * DD + dt * 32 + dl) * LSEG + jt * 32 + jq;
        *(__nv_bfloat162*)(g_Vth + off) = h0;
        *(__nv_bfloat162*)(g_Vth + off + 2) = h1;
        *(__nv_bfloat162*)(g_Vtl + off) = l0;
        *(__nv_bfloat162*)(g_Vtl + off + 2) = l1;
    }
}

// ================= Phase 2: mma.sync bf16-split causal attention ============
#define OQH 0
#define OQL 32768
#define OKH 65536
#define OKL 98304
#define OVH 131072
#define OVL 163840
#define OPH 196608
#define OPL 204800
#define OLS 212992
#define SM_TOTAL (OLS + 512)

__global__ __launch_bounds__(256, 1) void attn_kernel()
{
    extern __shared__ char smem[];
    const uint32_t sb = smem_to_u32(smem);
    float* lsum2 = (float*)(smem + OLS);

    const int t = threadIdx.x, lane = t & 31, wid = t >> 5;
    const int qt = 31 - (int)blockIdx.x;          // heavy tiles first
    const int s  = blockIdx.y;
    int batch, posbase, r;
    slot_decode(s, batch, posbase, r);
    const long qkvoff = (long)batch * (NN * DD);

    auto issueK = [&](int kt) {
#pragma unroll
        for (int sp = 0; sp < 2; sp++)
#pragma unroll
            for (int i = 0; i < 8; i++) {
                int e = t + i * 256;
                int key = e >> 5, c16 = e & 31;
                cp16(swz512(sb + (sp ? OKL : OKH), key, c16),
                     (sp ? g_Kl : g_Kh) + qkvoff +
                     ((long)(posbase + (kt * 64 + key) * r)) * DD + c16 * 8);
            }
    };
    auto issueV = [&](int kt) {
#pragma unroll
        for (int sp = 0; sp < 2; sp++)
#pragma unroll
            for (int i = 0; i < 8; i++) {
                int e = t + i * 256;
                int d = e >> 3, c16 = e & 7;
                cp16(swz128(sb + (sp ? OVL : OVH), d, c16),
                     (sp ? g_Vtl : g_Vth) + (long)s * DD * LSEG +
                     (long)d * LSEG + kt * 64 + c16 * 8);
            }
    };

    // prologue: Q tile + K(0)
    {
#pragma unroll
        for (int sp = 0; sp < 2; sp++)
#pragma unroll
            for (int i = 0; i < 8; i++) {
                int e = t + i * 256;
                int row = e >> 5, c16 = e & 31;
                cp16(swz512(sb + (sp ? OQL : OQH), row, c16),
                     (sp ? g_Ql : g_Qh) + qkvoff +
                     ((long)(posbase + (qt * 64 + row) * r)) * DD + c16 * 8);
            }
        CP_COMMIT();
        issueK(0); CP_COMMIT();
    }

    const int g = lane >> 2, cpair = 2 * (lane & 3);
    const int wq = wid & 3, wk = wid >> 2;
    float accd[4][4][4];
#pragma unroll
    for (int mt = 0; mt < 4; mt++)
#pragma unroll
        for (int nt = 0; nt < 4; nt++)
#pragma unroll
            for (int c = 0; c < 4; c++) accd[mt][nt][c] = 0.f;
    float rs0 = 0.f, rs1 = 0.f;

    for (int kt = 0; kt <= qt; kt++) {
        __syncthreads();                          // V buf free (prev PV done)
        issueV(kt); CP_COMMIT();
        CP_WAIT1();                               // Q + K(kt) landed
        __syncthreads();

        // ---- S = Q K^T: warp does 16q x 32k, 3 split terms ---------------
        float sacc[4][4];
#pragma unroll
        for (int nt = 0; nt < 4; nt++)
#pragma unroll
            for (int c = 0; c < 4; c++) sacc[nt][c] = 0.f;
#pragma unroll 2
        for (int kp = 0; kp < 8; kp++) {
            uint32_t ah0[4], ah1[4], al0[4], al1[4];
            ldsm4(ah0, aAddr(sb + OQH, 512, wq * 16, 2 * kp,     lane));
            ldsm4(ah1, aAddr(sb + OQH, 512, wq * 16, 2 * kp + 1, lane));
            ldsm4(al0, aAddr(sb + OQL, 512, wq * 16, 2 * kp,     lane));
            ldsm4(al1, aAddr(sb + OQL, 512, wq * 16, 2 * kp + 1, lane));
#pragma unroll
            for (int nt = 0; nt < 4; nt++) {
                uint32_t bh[4], bl[4];
                ldsm4(bh, b4Addr(sb + OKH, 512, wk * 32 + nt * 8, kp, lane));
                ldsm4(bl, b4Addr(sb + OKL, 512, wk * 32 + nt * 8, kp, lane));
                mma_bf16(sacc[nt], ah0, bh[0], bh[1]);
                mma_bf16(sacc[nt], ah0, bl[0], bl[1]);
                mma_bf16(sacc[nt], al0, bh[0], bh[1]);
                mma_bf16(sacc[nt], ah1, bh[2], bh[3]);
                mma_bf16(sacc[nt], ah1, bl[2], bl[3]);
                mma_bf16(sacc[nt], al1, bh[2], bh[3]);
            }
        }

        // ---- softmax ------------------------------------------------------
        const int prow0 = wq * 16 + g, prow1 = prow0 + 8;
        const int qrow0 = qt * 64 + prow0, qrow1 = qt * 64 + prow1;
#pragma unroll
        for (int nt = 0; nt < 4; nt++) {
            int kcol = wk * 32 + nt * 8 + cpair;
            int kg = kt * 64 + kcol;
            float p00 = (kg     <= qrow0) ? __expf(sacc[nt][0]) : 0.f;
            float p01 = (kg + 1 <= qrow0) ? __expf(sacc[nt][1]) : 0.f;
            float p10 = (kg     <= qrow1) ? __expf(sacc[nt][2]) : 0.f;
            float p11 = (kg + 1 <= qrow1) ? __expf(sacc[nt][3]) : 0.f;
            rs0 += p00 + p01;
            rs1 += p10 + p11;
            __nv_bfloat162 h0 = __floats2bfloat162_rn(p00, p01);
            __nv_bfloat162 l0 = __floats2bfloat162_rn(p00 - __bfloat162float(h0.x),
                                                      p01 - __bfloat162float(h0.y));
            __nv_bfloat162 h1 = __floats2bfloat162_rn(p10, p11);
            __nv_bfloat162 l1 = __floats2bfloat162_rn(p10 - __bfloat162float(h1.x),
                                                      p11 - __bfloat162float(h1.y));
            uint32_t ob0 = prow0 * 128 + ((uint32_t)((kcol >> 3) ^ (prow0 & 7)) << 4)
                         + (kcol & 7) * 2;
            uint32_t ob1 = prow1 * 128 + ((uint32_t)((kcol >> 3) ^ (prow1 & 7)) << 4)
                         + (kcol & 7) * 2;
            *(__nv_bfloat162*)(smem + OPH + ob0) = h0;
            *(__nv_bfloat162*)(smem + OPL + ob0) = l0;
            *(__nv_bfloat162*)(smem + OPH + ob1) = h1;
            *(__nv_bfloat162*)(smem + OPL + ob1) = l1;
        }
        __syncthreads();                          // P visible; K buf free

        // ---- prefetch next K (overlaps PV), then wait V --------------------
        if (kt < qt) { issueK(kt + 1); CP_COMMIT(); CP_WAIT1(); }
        else CP_WAIT0();
        __syncthreads();                          // V visible to all

        // ---- D += P V: warp owns 32 d-cols, all 64 q rows ------------------
        const int n0 = wid * 32;
#pragma unroll
        for (int kp = 0; kp < 2; kp++) {
            uint32_t bh[4][4], bl[4][4];
#pragma unroll
            for (int nt = 0; nt < 4; nt++) {
                ldsm4(bh[nt], b4Addr(sb + OVH, 128, n0 + nt * 8, kp, lane));
                ldsm4(bl[nt], b4Addr(sb + OVL, 128, n0 + nt * 8, kp, lane));
            }
#pragma unroll
            for (int mt = 0; mt < 4; mt++) {
                uint32_t ah0[4], ah1[4], al0[4], al1[4];
                ldsm4(ah0, aAddr(sb + OPH, 128, mt * 16, 2 * kp,     lane));
                ldsm4(ah1, aAddr(sb + OPH, 128, mt * 16, 2 * kp + 1, lane));
                ldsm4(al0, aAddr(sb + OPL, 128, mt * 16, 2 * kp,     lane));
                ldsm4(al1, aAddr(sb + OPL, 128, mt * 16, 2 * kp + 1, lane));
#pragma unroll
                for (int nt = 0; nt < 4; nt++) {
                    mma_bf16(accd[mt][nt], ah0, bh[nt][0], bh[nt][1]);
                    mma_bf16(accd[mt][nt], ah0, bl[nt][0], bl[nt][1]);
                    mma_bf16(accd[mt][nt], al0, bh[nt][0], bh[nt][1]);
                    mma_bf16(accd[mt][nt], ah1, bh[nt][2], bh[nt][3]);
                    mma_bf16(accd[mt][nt], ah1, bl[nt][2], bl[nt][3]);
                    mma_bf16(accd[mt][nt], al1, bh[nt][2], bh[nt][3]);
                }
            }
        }
    }

    // ---- epilogue ---------------------------------------------------------
    rs0 += __shfl_xor_sync(0xffffffffu, rs0, 1);
    rs0 += __shfl_xor_sync(0xffffffffu, rs0, 2);
    rs1 += __shfl_xor_sync(0xffffffffu, rs1, 1);
    rs1 += __shfl_xor_sync(0xffffffffu, rs1, 2);
    if ((lane & 3) == 0) {
        lsum2[wk * 64 + wq * 16 + g]     = rs0;
        lsum2[wk * 64 + wq * 16 + g + 8] = rs1;
    }
    __syncthreads();

#pragma unroll
    for (int mt = 0; mt < 4; mt++) {
        int lr0 = mt * 16 + g, lr1 = lr0 + 8;
        float inv0 = 1.0f / (lsum2[lr0] + lsum2[64 + lr0]);
        float inv1 = 1.0f / (lsum2[lr1] + lsum2[64 + lr1]);
        long ro0 = (long)(s * LSEG + qt * 64 + lr0) * DD;
        long ro1 = (long)(s * LSEG + qt * 64 + lr1) * DD;
#pragma unroll
        for (int nt = 0; nt < 4; nt++) {
            int col = wid * 32 + nt * 8 + cpair;
            *(float2*)(g_O + ro0 + col) =
                make_float2(accd[mt][nt][0] * inv0, accd[mt][nt][1] * inv0);
            *(float2*)(g_O + ro1 + col) =
                make_float2(accd[mt][nt][2] * inv1, accd[mt][nt][3] * inv1);
        }
    }
    if (t < 64)
        g_den[s * LSEG + qt * 64 + t] = lsum2[t] + lsum2[64 + t];
}

// ================= Phase 3: combine (gather) ================================
__global__ __launch_bounds__(256) void combine_kernel(float* __restrict__ out)
{
    const int token = blockIdx.x * 4 + (threadIdx.x >> 6);
    const int lane  = threadIdx.x & 63;
    const int b = token >> 13, p = token & 8191;

    const int slot0 = (p >> 11) * 4 + b, j0 = p & 2047;
    float d0 = g_den[slot0 * LSEG + j0];
    float sum = d0;
    int slot1 = -1, j1 = 0, slot2 = -1, j2 = 0;
    float d1 = 0.f, d2 = 0.f;
    if ((p & 1) == 0) {
        slot1 = 16 + (p >> 12) * 4 + b; j1 = (p & 4095) >> 1;
        d1 = g_den[slot1 * LSEG + j1]; sum += d1;
    }
    if ((p & 3) == 0) {
        slot2 = 24 + b; j2 = p >> 2;
        d2 = g_den[slot2 * LSEG + j2]; sum += d2;
    }
    const float inv = 1.0f / sum;
    const int c = lane << 2;

    float4 o0 = *(const float4*)(g_O + ((long)slot0 * LSEG + j0) * DD + c);
    float a0 = d0 * inv;
    float4 res;
    res.x = o0.x * a0; res.y = o0.y * a0; res.z = o0.z * a0; res.w = o0.w * a0;
    if (slot1 >= 0) {
        float4 o1 = *(const float4*)(g_O + ((long)slot1 * LSEG + j1) * DD + c);
        float a1 = d1 * inv;
        res.x = fmaf(o1.x, a1, res.x); res.y = fmaf(o1.y, a1, res.y);
        res.z = fmaf(o1.z, a1, res.z); res.w = fmaf(o1.w, a1, res.w);
    }
    if (slot2 >= 0) {
        float4 o2v = *(const float4*)(g_O + ((long)slot2 * LSEG + j2) * DD + c);
        float a2 = d2 * inv;
        res.x = fmaf(o2v.x, a2, res.x); res.y = fmaf(o2v.y, a2, res.y);
        res.z = fmaf(o2v.z, a2, res.z); res.w = fmaf(o2v.w, a2, res.w);
    }
    *(float4*)(out + ((long)b * NN + p) * DD + c) = res;
}

// ================= launch ====================================================
extern "C" void kernel_launch(void* const* d_in, const int* in_sizes, int n_in,
                              void* d_out, int out_size)
{
    (void)in_sizes; (void)n_in; (void)out_size;
    const float* x  = (const float*)d_in[0];
    const float* Wq = (const float*)d_in[1];
    const float* Wk = (const float*)d_in[2];
    const float* Wv = (const float*)d_in[3];

    cudaFuncSetAttribute(qkv_mma_kernel, cudaFuncAttributeMaxDynamicSharedMemorySize,
                         QKV_SMEM);
    cudaFuncSetAttribute(attn_kernel, cudaFuncAttributeMaxDynamicSharedMemorySize,
                         SM_TOTAL);

    split_x_kernel<<<8192, 256>>>(x);
    split_w_kernel<<<dim3(8, 8, 3), 256>>>(Wq, Wk, Wv);
    qkv_mma_kernel<<<dim3(256, 2, 3), 256, QKV_SMEM>>>();
    transpose_v_kernel<<<dim3(64, 8, 28), 256>>>();
    attn_kernel<<<dim3(32, 28), 256, SM_TOTAL>>>();
    combine_kernel<<<8192, 256>>>((float*)d_out);
}

// round 9
// speedup vs baseline: 3.7065x; 1.1037x over previous
#include <cuda_runtime.h>
#include <cuda_bf16.h>
#include <cuda_fp16.h>
#include <stdint.h>
#include <math.h>

#define BB   4
#define NN   8192
#define CC   256
#define DD   256
#define LSEG 2048
#define NSEG 28

// ---------------- cp.async helpers -----------------------------------------
__device__ __forceinline__ uint32_t smem_to_u32(const void* p) {
    uint32_t a;
    asm("{ .reg .u64 t; cvta.to.shared.u64 t, %1; cvt.u32.u64 %0, t; }"
        : "=r"(a) : "l"(p));
    return a;
}
__device__ __forceinline__ void cp16(uint32_t dst, const void* src) {
    asm volatile("cp.async.cg.shared.global [%0], [%1], 16;" :: "r"(dst), "l"(src) : "memory");
}
#define CP_COMMIT() asm volatile("cp.async.commit_group;" ::: "memory")
#define CP_WAIT1()  asm volatile("cp.async.wait_group 1;" ::: "memory")
#define CP_WAIT0()  asm volatile("cp.async.wait_group 0;" ::: "memory")

// ---------------- ldmatrix / mma.sync ---------------------------------------
__device__ __forceinline__ void ldsm4(uint32_t (&d)[4], uint32_t addr) {
    asm volatile("ldmatrix.sync.aligned.m8n8.x4.shared.b16 {%0,%1,%2,%3}, [%4];"
        : "=r"(d[0]), "=r"(d[1]), "=r"(d[2]), "=r"(d[3]) : "r"(addr));
}
__device__ __forceinline__ void mma_bf16(float (&c)[4], const uint32_t (&a)[4],
                                         uint32_t b0, uint32_t b1) {
    asm volatile("mma.sync.aligned.m16n8k16.row.col.f32.bf16.bf16.f32 "
        "{%0,%1,%2,%3}, {%4,%5,%6,%7}, {%8,%9}, {%0,%1,%2,%3};"
        : "+f"(c[0]), "+f"(c[1]), "+f"(c[2]), "+f"(c[3])
        : "r"(a[0]), "r"(a[1]), "r"(a[2]), "r"(a[3]), "r"(b0), "r"(b1));
}
__device__ __forceinline__ void mma_fp16(float (&c)[4], const uint32_t (&a)[4],
                                         uint32_t b0, uint32_t b1) {
    asm volatile("mma.sync.aligned.m16n8k16.row.col.f32.f16.f16.f32 "
        "{%0,%1,%2,%3}, {%4,%5,%6,%7}, {%8,%9}, {%0,%1,%2,%3};"
        : "+f"(c[0]), "+f"(c[1]), "+f"(c[2]), "+f"(c[3])
        : "r"(a[0]), "r"(a[1]), "r"(a[2]), "r"(a[3]), "r"(b0), "r"(b1));
}

// A-fragment address (ldmatrix x4): 16 rows starting r0, k-step ks (16 elems)
__device__ __forceinline__ uint32_t aAddr(uint32_t base, int rowbytes, int r0,
                                          int ks, int lane) {
    int row = r0 + (lane & 7) + ((lane & 8) ? 8 : 0);
    int c16 = ks * 2 + (lane >> 4);
    return base + row * rowbytes + ((uint32_t)(c16 ^ (row & 7)) << 4);
}
// B-fragment address (ldmatrix x4): 8 rows at n0, TWO k-steps (pair kp)
__device__ __forceinline__ uint32_t b4Addr(uint32_t base, int rowbytes, int n0,
                                           int kp, int lane) {
    int row = n0 + (lane & 7);
    int c16 = kp * 4 + (lane >> 3);
    return base + row * rowbytes + ((uint32_t)(c16 ^ (row & 7)) << 4);
}
__device__ __forceinline__ uint32_t swz512(uint32_t base, int row, int c16) {
    return base + row * 512 + ((uint32_t)(c16 ^ (row & 7)) << 4);
}
__device__ __forceinline__ uint32_t swz128(uint32_t base, int row, int c16) {
    return base + row * 128 + ((uint32_t)(c16 ^ (row & 7)) << 4);
}

// ---------------- scratch ---------------------------------------------------
__device__ __nv_bfloat16 g_Xh[BB * NN * CC];
__device__ __nv_bfloat16 g_Xl[BB * NN * CC];
__device__ __nv_bfloat16 g_Wht[3 * CC * DD];        // [z][n][k] transposed
__device__ __nv_bfloat16 g_Wlt[3 * CC * DD];
__device__ __nv_bfloat16 g_Qh[BB * NN * DD];
__device__ __nv_bfloat16 g_Ql[BB * NN * DD];
__device__ __nv_bfloat16 g_Kh[BB * NN * DD];
__device__ __nv_bfloat16 g_Kl[BB * NN * DD];
__device__ float         g_V [BB * NN * DD];
__device__ __half        g_Vth[NSEG * DD * LSEG];   // per-slot V^T, fp16 hi
__device__ __half        g_Vtl[NSEG * DD * LSEG];   // per-slot V^T, fp16 lo
__device__ float g_O[NSEG * LSEG * DD];
__device__ float g_den[NSEG * LSEG];

__device__ __forceinline__ void slot_decode(int s, int& batch, int& posbase, int& r) {
    int w, base;
    if (s < 16)      { w = 2048; r = 1; base = 0;  }
    else if (s < 24) { w = 4096; r = 2; base = 16; }
    else             { w = 8192; r = 4; base = 24; }
    int local = s - base;
    batch = local & 3;
    posbase = (local >> 2) * w;
}

// ================= Phase 0a: split X into bf16 hi/lo ========================
__global__ __launch_bounds__(256) void split_x_kernel(const float* __restrict__ X)
{
    long e = (long)blockIdx.x * 1024 + threadIdx.x * 4;
    float4 v = *(const float4*)(X + e);
    __nv_bfloat162 h0 = __floats2bfloat162_rn(v.x, v.y);
    __nv_bfloat162 h1 = __floats2bfloat162_rn(v.z, v.w);
    __nv_bfloat162 l0 = __floats2bfloat162_rn(v.x - __bfloat162float(h0.x),
                                              v.y - __bfloat162float(h0.y));
    __nv_bfloat162 l1 = __floats2bfloat162_rn(v.z - __bfloat162float(h1.x),
                                              v.w - __bfloat162float(h1.y));
    *(__nv_bfloat162*)(g_Xh + e) = h0; *(__nv_bfloat162*)(g_Xh + e + 2) = h1;
    *(__nv_bfloat162*)(g_Xl + e) = l0; *(__nv_bfloat162*)(g_Xl + e + 2) = l1;
}

// ================= Phase 0b: transpose+split W ==============================
__global__ __launch_bounds__(256) void split_w_kernel(
    const float* __restrict__ Wq, const float* __restrict__ Wk,
    const float* __restrict__ Wv)
{
    __shared__ float T[32][33];
    const int z = blockIdx.z;
    const float* W = (z == 0) ? Wq : (z == 1) ? Wk : Wv;
    const int k0 = blockIdx.x * 32, n0 = blockIdx.y * 32;
    const int t = threadIdx.x;
    {
        int kk = t >> 3, n4 = (t & 7) << 2;
        float4 v = *(const float4*)(W + (long)(k0 + kk) * DD + n0 + n4);
        T[kk][n4] = v.x; T[kk][n4 + 1] = v.y; T[kk][n4 + 2] = v.z; T[kk][n4 + 3] = v.w;
    }
    __syncthreads();
    {
        int nn = t >> 3, k4 = (t & 7) << 2;
        float sc = (z == 0) ? 0.0625f : 1.0f;
        float v0 = T[k4][nn] * sc, v1 = T[k4 + 1][nn] * sc;
        float v2 = T[k4 + 2][nn] * sc, v3 = T[k4 + 3][nn] * sc;
        __nv_bfloat162 h0 = __floats2bfloat162_rn(v0, v1);
        __nv_bfloat162 h1 = __floats2bfloat162_rn(v2, v3);
        __nv_bfloat162 l0 = __floats2bfloat162_rn(v0 - __bfloat162float(h0.x),
                                                  v1 - __bfloat162float(h0.y));
        __nv_bfloat162 l1 = __floats2bfloat162_rn(v2 - __bfloat162float(h1.x),
                                                  v3 - __bfloat162float(h1.y));
        long off = (long)z * (CC * DD) + (long)(n0 + nn) * CC + k0 + k4;
        *(__nv_bfloat162*)(g_Wht + off) = h0; *(__nv_bfloat162*)(g_Wht + off + 2) = h1;
        *(__nv_bfloat162*)(g_Wlt + off) = l0; *(__nv_bfloat162*)(g_Wlt + off + 2) = l1;
    }
}

// ================= Phase 1: QKV projection via mma.sync =====================
#define GX_H 0
#define GX_L 32768
#define GW_H 65536
#define GW_L 98304
#define QKV_SMEM 131072

__global__ __launch_bounds__(256, 1) void qkv_mma_kernel()
{
    extern __shared__ char smem[];
    const uint32_t sb = smem_to_u32(smem);
    const int t = threadIdx.x, lane = t & 31, wid = t >> 5;
    const int m0 = blockIdx.x * 128, n0 = blockIdx.y * 128, z = blockIdx.z;
    const __nv_bfloat16* Wh = g_Wht + (long)z * (CC * DD);
    const __nv_bfloat16* Wl = g_Wlt + (long)z * (CC * DD);

    auto loadslab = [&](int s, int buf) {
        int k0 = s * 64;
        uint32_t bo = (uint32_t)buf * 16384;
#pragma unroll
        for (int i = 0; i < 4; i++) {
            int e = t + i * 256;
            int row = e >> 3, c16 = e & 7;
            long xs = (long)(m0 + row) * CC + k0 + c16 * 8;
            cp16(swz128(sb + GX_H + bo, row, c16), g_Xh + xs);
            cp16(swz128(sb + GX_L + bo, row, c16), g_Xl + xs);
            long ws = (long)(n0 + row) * CC + k0 + c16 * 8;
            cp16(swz128(sb + GW_H + bo, row, c16), Wh + ws);
            cp16(swz128(sb + GW_L + bo, row, c16), Wl + ws);
        }
    };

    float acc[16][4];
#pragma unroll
    for (int nt = 0; nt < 16; nt++)
#pragma unroll
        for (int c = 0; c < 4; c++) acc[nt][c] = 0.f;

    loadslab(0, 0); CP_COMMIT();
    for (int s = 0; s < 4; s++) {
        if (s < 3) { loadslab(s + 1, (s + 1) & 1); CP_COMMIT(); CP_WAIT1(); }
        else CP_WAIT0();
        __syncthreads();
        uint32_t bo = (uint32_t)(s & 1) * 16384;
#pragma unroll
        for (int kp = 0; kp < 2; kp++) {
            uint32_t ah0[4], ah1[4], al0[4], al1[4];
            ldsm4(ah0, aAddr(sb + GX_H + bo, 128, wid * 16, 2 * kp,     lane));
            ldsm4(ah1, aAddr(sb + GX_H + bo, 128, wid * 16, 2 * kp + 1, lane));
            ldsm4(al0, aAddr(sb + GX_L + bo, 128, wid * 16, 2 * kp,     lane));
            ldsm4(al1, aAddr(sb + GX_L + bo, 128, wid * 16, 2 * kp + 1, lane));
#pragma unroll
            for (int nt = 0; nt < 16; nt++) {
                uint32_t bh[4], bl[4];
                ldsm4(bh, b4Addr(sb + GW_H + bo, 128, nt * 8, kp, lane));
                ldsm4(bl, b4Addr(sb + GW_L + bo, 128, nt * 8, kp, lane));
                mma_bf16(acc[nt], ah0, bh[0], bh[1]);
                mma_bf16(acc[nt], ah0, bl[0], bl[1]);
                mma_bf16(acc[nt], al0, bh[0], bh[1]);
                mma_bf16(acc[nt], ah1, bh[2], bh[3]);
                mma_bf16(acc[nt], ah1, bl[2], bl[3]);
                mma_bf16(acc[nt], al1, bh[2], bh[3]);
            }
        }
        __syncthreads();
    }

    const int g = lane >> 2, cpair = 2 * (lane & 3);
#pragma unroll
    for (int nt = 0; nt < 16; nt++) {
        long r0 = (long)(m0 + wid * 16 + g) * DD + n0 + nt * 8 + cpair;
        long r1 = r0 + 8 * DD;
        if (z == 2) {
            *(float2*)(g_V + r0) = make_float2(acc[nt][0], acc[nt][1]);
            *(float2*)(g_V + r1) = make_float2(acc[nt][2], acc[nt][3]);
        } else {
            __nv_bfloat162 h0 = __floats2bfloat162_rn(acc[nt][0], acc[nt][1]);
            __nv_bfloat162 l0 = __floats2bfloat162_rn(acc[nt][0] - __bfloat162float(h0.x),
                                                      acc[nt][1] - __bfloat162float(h0.y));
            __nv_bfloat162 h1 = __floats2bfloat162_rn(acc[nt][2], acc[nt][3]);
            __nv_bfloat162 l1 = __floats2bfloat162_rn(acc[nt][2] - __bfloat162float(h1.x),
                                                      acc[nt][3] - __bfloat162float(h1.y));
            if (z == 0) {
                *(__nv_bfloat162*)(g_Qh + r0) = h0; *(__nv_bfloat162*)(g_Ql + r0) = l0;
                *(__nv_bfloat162*)(g_Qh + r1) = h1; *(__nv_bfloat162*)(g_Ql + r1) = l1;
            } else {
                *(__nv_bfloat162*)(g_Kh + r0) = h0; *(__nv_bfloat162*)(g_Kl + r0) = l0;
                *(__nv_bfloat162*)(g_Kh + r1) = h1; *(__nv_bfloat162*)(g_Kl + r1) = l1;
            }
        }
    }
}

// ================= Phase 1b: per-slot V^T gather + fp16 split ===============
__global__ __launch_bounds__(256) void transpose_v_kernel()
{
    __shared__ float T[32][36];
    const int s = blockIdx.z, jt = blockIdx.x, dt = blockIdx.y;
    int batch, posbase, r;
    slot_decode(s, batch, posbase, r);

    const int t = threadIdx.x;
    {
        int jl = t >> 3, dq = (t & 7) << 2;
        int pos = posbase + (jt * 32 + jl) * r;
        float4 v = *(const float4*)(g_V + ((long)batch * NN + pos) * DD + dt * 32 + dq);
        T[jl][dq] = v.x; T[jl][dq + 1] = v.y; T[jl][dq + 2] = v.z; T[jl][dq + 3] = v.w;
    }
    __syncthreads();
    {
        int dl = t >> 3, jq = (t & 7) << 2;
        float v0 = T[jq][dl], v1 = T[jq + 1][dl], v2 = T[jq + 2][dl], v3 = T[jq + 3][dl];
        __half2 h0 = __floats2half2_rn(v0, v1);
        __half2 h1 = __floats2half2_rn(v2, v3);
        __half2 l0 = __floats2half2_rn(v0 - __half2float(h0.x),
                                       v1 - __half2float(h0.y));
        __half2 l1 = __floats2half2_rn(v2 - __half2float(h1.x),
                                       v3 - __half2float(h1.y));
        long off = ((long)s * DD + dt * 32 + dl) * LSEG + jt * 32 + jq;
        *(__half2*)(g_Vth + off) = h0;
        *(__half2*)(g_Vth + off + 2) = h1;
        *(__half2*)(g_Vtl + off) = l0;
        *(__half2*)(g_Vtl + off + 2) = l1;
    }
}

// ================= Phase 2: mma.sync split-precision causal attention =======
// S: 3-term bf16 (hh+hl+lh).  PV: P single fp16 x V fp16 (hi+lo), 2 terms.
#define OQH 0
#define OQL 32768
#define OKH 65536
#define OKL 98304
#define OVH 131072
#define OVL 163840
#define OPH 196608
#define OLS 204800
#define SM_TOTAL (OLS + 512)

__global__ __launch_bounds__(256, 1) void attn_kernel()
{
    extern __shared__ char smem[];
    const uint32_t sb = smem_to_u32(smem);
    float* lsum2 = (float*)(smem + OLS);

    const int t = threadIdx.x, lane = t & 31, wid = t >> 5;
    const int qt = 31 - (int)blockIdx.x;          // heavy tiles first
    const int s  = blockIdx.y;
    int batch, posbase, r;
    slot_decode(s, batch, posbase, r);
    const long qkvoff = (long)batch * (NN * DD);

    auto issueK = [&](int kt) {
#pragma unroll
        for (int sp = 0; sp < 2; sp++)
#pragma unroll
            for (int i = 0; i < 8; i++) {
                int e = t + i * 256;
                int key = e >> 5, c16 = e & 31;
                cp16(swz512(sb + (sp ? OKL : OKH), key, c16),
                     (sp ? g_Kl : g_Kh) + qkvoff +
                     ((long)(posbase + (kt * 64 + key) * r)) * DD + c16 * 8);
            }
    };
    auto issueV = [&](int kt) {
#pragma unroll
        for (int sp = 0; sp < 2; sp++)
#pragma unroll
            for (int i = 0; i < 8; i++) {
                int e = t + i * 256;
                int d = e >> 3, c16 = e & 7;
                cp16(swz128(sb + (sp ? OVL : OVH), d, c16),
                     (const void*)((sp ? g_Vtl : g_Vth) + (long)s * DD * LSEG +
                                   (long)d * LSEG + kt * 64 + c16 * 8));
            }
    };

    // prologue: Q tile + K(0)
    {
#pragma unroll
        for (int sp = 0; sp < 2; sp++)
#pragma unroll
            for (int i = 0; i < 8; i++) {
                int e = t + i * 256;
                int row = e >> 5, c16 = e & 31;
                cp16(swz512(sb + (sp ? OQL : OQH), row, c16),
                     (sp ? g_Ql : g_Qh) + qkvoff +
                     ((long)(posbase + (qt * 64 + row) * r)) * DD + c16 * 8);
            }
        CP_COMMIT();
        issueK(0); CP_COMMIT();
    }

    const int g = lane >> 2, cpair = 2 * (lane & 3);
    const int wq = wid & 3, wk = wid >> 2;
    float accd[4][4][4];
#pragma unroll
    for (int mt = 0; mt < 4; mt++)
#pragma unroll
        for (int nt = 0; nt < 4; nt++)
#pragma unroll
            for (int c = 0; c < 4; c++) accd[mt][nt][c] = 0.f;
    float rs0 = 0.f, rs1 = 0.f;

    for (int kt = 0; kt <= qt; kt++) {
        __syncthreads();                          // V buf free (prev PV done)
        issueV(kt); CP_COMMIT();
        CP_WAIT1();                               // Q + K(kt) landed
        __syncthreads();

        // ---- S = Q K^T: warp does 16q x 32k, 3 bf16 split terms -----------
        float sacc[4][4];
#pragma unroll
        for (int nt = 0; nt < 4; nt++)
#pragma unroll
            for (int c = 0; c < 4; c++) sacc[nt][c] = 0.f;
#pragma unroll 2
        for (int kp = 0; kp < 8; kp++) {
            uint32_t ah0[4], ah1[4], al0[4], al1[4];
            ldsm4(ah0, aAddr(sb + OQH, 512, wq * 16, 2 * kp,     lane));
            ldsm4(ah1, aAddr(sb + OQH, 512, wq * 16, 2 * kp + 1, lane));
            ldsm4(al0, aAddr(sb + OQL, 512, wq * 16, 2 * kp,     lane));
            ldsm4(al1, aAddr(sb + OQL, 512, wq * 16, 2 * kp + 1, lane));
#pragma unroll
            for (int nt = 0; nt < 4; nt++) {
                uint32_t bh[4], bl[4];
                ldsm4(bh, b4Addr(sb + OKH, 512, wk * 32 + nt * 8, kp, lane));
                ldsm4(bl, b4Addr(sb + OKL, 512, wk * 32 + nt * 8, kp, lane));
                mma_bf16(sacc[nt], ah0, bh[0], bh[1]);
                mma_bf16(sacc[nt], ah0, bl[0], bl[1]);
                mma_bf16(sacc[nt], al0, bh[0], bh[1]);
                mma_bf16(sacc[nt], ah1, bh[2], bh[3]);
                mma_bf16(sacc[nt], ah1, bl[2], bl[3]);
                mma_bf16(sacc[nt], al1, bh[2], bh[3]);
            }
        }

        // ---- softmax: mask, exp, row-sum, pack P (single fp16) -------------
        const int prow0 = wq * 16 + g, prow1 = prow0 + 8;
        const int qrow0 = qt * 64 + prow0, qrow1 = qt * 64 + prow1;
#pragma unroll
        for (int nt = 0; nt < 4; nt++) {
            int kcol = wk * 32 + nt * 8 + cpair;
            int kg = kt * 64 + kcol;
            float p00 = (kg     <= qrow0) ? __expf(sacc[nt][0]) : 0.f;
            float p01 = (kg + 1 <= qrow0) ? __expf(sacc[nt][1]) : 0.f;
            float p10 = (kg     <= qrow1) ? __expf(sacc[nt][2]) : 0.f;
            float p11 = (kg + 1 <= qrow1) ? __expf(sacc[nt][3]) : 0.f;
            rs0 += p00 + p01;
            rs1 += p10 + p11;
            __half2 h0 = __floats2half2_rn(p00, p01);
            __half2 h1 = __floats2half2_rn(p10, p11);
            uint32_t ob0 = prow0 * 128 + ((uint32_t)((kcol >> 3) ^ (prow0 & 7)) << 4)
                         + (kcol & 7) * 2;
            uint32_t ob1 = prow1 * 128 + ((uint32_t)((kcol >> 3) ^ (prow1 & 7)) << 4)
                         + (kcol & 7) * 2;
            *(__half2*)(smem + OPH + ob0) = h0;
            *(__half2*)(smem + OPH + ob1) = h1;
        }
        __syncthreads();                          // P visible; K buf free

        // ---- prefetch next K (overlaps PV), then wait V --------------------
        if (kt < qt) { issueK(kt + 1); CP_COMMIT(); CP_WAIT1(); }
        else CP_WAIT0();
        __syncthreads();                          // V visible to all

        // ---- D += P V: warp owns 32 d-cols; fp16, 2 terms (P*Vh + P*Vl) ----
        const int n0 = wid * 32;
#pragma unroll
        for (int kp = 0; kp < 2; kp++) {
            uint32_t bh[4][4], bl[4][4];
#pragma unroll
            for (int nt = 0; nt < 4; nt++) {
                ldsm4(bh[nt], b4Addr(sb + OVH, 128, n0 + nt * 8, kp, lane));
                ldsm4(bl[nt], b4Addr(sb + OVL, 128, n0 + nt * 8, kp, lane));
            }
#pragma unroll
            for (int mt = 0; mt < 4; mt++) {
                uint32_t ah0[4], ah1[4];
                ldsm4(ah0, aAddr(sb + OPH, 128, mt * 16, 2 * kp,     lane));
                ldsm4(ah1, aAddr(sb + OPH, 128, mt * 16, 2 * kp + 1, lane));
#pragma unroll
                for (int nt = 0; nt < 4; nt++) {
                    mma_fp16(accd[mt][nt], ah0, bh[nt][0], bh[nt][1]);
                    mma_fp16(accd[mt][nt], ah0, bl[nt][0], bl[nt][1]);
                    mma_fp16(accd[mt][nt], ah1, bh[nt][2], bh[nt][3]);
                    mma_fp16(accd[mt][nt], ah1, bl[nt][2], bl[nt][3]);
                }
            }
        }
    }

    // ---- epilogue ---------------------------------------------------------
    rs0 += __shfl_xor_sync(0xffffffffu, rs0, 1);
    rs0 += __shfl_xor_sync(0xffffffffu, rs0, 2);
    rs1 += __shfl_xor_sync(0xffffffffu, rs1, 1);
    rs1 += __shfl_xor_sync(0xffffffffu, rs1, 2);
    if ((lane & 3) == 0) {
        lsum2[wk * 64 + wq * 16 + g]     = rs0;
        lsum2[wk * 64 + wq * 16 + g + 8] = rs1;
    }
    __syncthreads();

#pragma unroll
    for (int mt = 0; mt < 4; mt++) {
        int lr0 = mt * 16 + g, lr1 = lr0 + 8;
        float inv0 = 1.0f / (lsum2[lr0] + lsum2[64 + lr0]);
        float inv1 = 1.0f / (lsum2[lr1] + lsum2[64 + lr1]);
        long ro0 = (long)(s * LSEG + qt * 64 + lr0) * DD;
        long ro1 = (long)(s * LSEG + qt * 64 + lr1) * DD;
#pragma unroll
        for (int nt = 0; nt < 4; nt++) {
            int col = wid * 32 + nt * 8 + cpair;
            *(float2*)(g_O + ro0 + col) =
                make_float2(accd[mt][nt][0] * inv0, accd[mt][nt][1] * inv0);
            *(float2*)(g_O + ro1 + col) =
                make_float2(accd[mt][nt][2] * inv1, accd[mt][nt][3] * inv1);
        }
    }
    if (t < 64)
        g_den[s * LSEG + qt * 64 + t] = lsum2[t] + lsum2[64 + t];
}

// ================= Phase 3: combine (gather) ================================
__global__ __launch_bounds__(256) void combine_kernel(float* __restrict__ out)
{
    const int token = blockIdx.x * 4 + (threadIdx.x >> 6);
    const int lane  = threadIdx.x & 63;
    const int b = token >> 13, p = token & 8191;

    const int slot0 = (p >> 11) * 4 + b, j0 = p & 2047;
    float d0 = g_den[slot0 * LSEG + j0];
    float sum = d0;
    int slot1 = -1, j1 = 0, slot2 = -1, j2 = 0;
    float d1 = 0.f, d2 = 0.f;
    if ((p & 1) == 0) {
        slot1 = 16 + (p >> 12) * 4 + b; j1 = (p & 4095) >> 1;
        d1 = g_den[slot1 * LSEG + j1]; sum += d1;
    }
    if ((p & 3) == 0) {
        slot2 = 24 + b; j2 = p >> 2;
        d2 = g_den[slot2 * LSEG + j2]; sum += d2;
    }
    const float inv = 1.0f / sum;
    const int c = lane << 2;

    float4 o0 = *(const float4*)(g_O + ((long)slot0 * LSEG + j0) * DD + c);
    float a0 = d0 * inv;
    float4 res;
    res.x = o0.x * a0; res.y = o0.y * a0; res.z = o0.z * a0; res.w = o0.w * a0;
    if (slot1 >= 0) {
        float4 o1 = *(const float4*)(g_O + ((long)slot1 * LSEG + j1) * DD + c);
        float a1 = d1 * inv;
        res.x = fmaf(o1.x, a1, res.x); res.y = fmaf(o1.y, a1, res.y);
        res.z = fmaf(o1.z, a1, res.z); res.w = fmaf(o1.w, a1, res.w);
    }
    if (slot2 >= 0) {
        float4 o2v = *(const float4*)(g_O + ((long)slot2 * LSEG + j2) * DD + c);
        float a2 = d2 * inv;
        res.x = fmaf(o2v.x, a2, res.x); res.y = fmaf(o2v.y, a2, res.y);
        res.z = fmaf(o2v.z, a2, res.z); res.w = fmaf(o2v.w, a2, res.w);
    }
    *(float4*)(out + ((long)b * NN + p) * DD + c) = res;
}

// ================= launch ====================================================
extern "C" void kernel_launch(void* const* d_in, const int* in_sizes, int n_in,
                              void* d_out, int out_size)
{
    (void)in_sizes; (void)n_in; (void)out_size;
    const float* x  = (const float*)d_in[0];
    const float* Wq = (const float*)d_in[1];
    const float* Wk = (const float*)d_in[2];
    const float* Wv = (const float*)d_in[3];

    cudaFuncSetAttribute(qkv_mma_kernel, cudaFuncAttributeMaxDynamicSharedMemorySize,
                         QKV_SMEM);
    cudaFuncSetAttribute(attn_kernel, cudaFuncAttributeMaxDynamicSharedMemorySize,
                         SM_TOTAL);

    split_x_kernel<<<8192, 256>>>(x);
    split_w_kernel<<<dim3(8, 8, 3), 256>>>(Wq, Wk, Wv);
    qkv_mma_kernel<<<dim3(256, 2, 3), 256, QKV_SMEM>>>();
    transpose_v_kernel<<<dim3(64, 8, 28), 256>>>();
    attn_kernel<<<dim3(32, 28), 256, SM_TOTAL>>>();
    combine_kernel<<<8192, 256>>>((float*)d_out);
}

// round 10
// speedup vs baseline: 4.5935x; 1.2393x over previous
#include <cuda_runtime.h>
#include <cuda_bf16.h>
#include <cuda_fp16.h>
#include <stdint.h>
#include <math.h>

#define BB   4
#define NN   8192
#define CC   256
#define DD   256
#define LSEG 2048
#define NSEG 28

// ---------------- cp.async helpers -----------------------------------------
__device__ __forceinline__ uint32_t smem_to_u32(const void* p) {
    uint32_t a;
    asm("{ .reg .u64 t; cvta.to.shared.u64 t, %1; cvt.u32.u64 %0, t; }"
        : "=r"(a) : "l"(p));
    return a;
}
__device__ __forceinline__ void cp16(uint32_t dst, const void* src) {
    asm volatile("cp.async.cg.shared.global [%0], [%1], 16;" :: "r"(dst), "l"(src) : "memory");
}
#define CP_COMMIT() asm volatile("cp.async.commit_group;" ::: "memory")
#define CP_WAIT1()  asm volatile("cp.async.wait_group 1;" ::: "memory")
#define CP_WAIT0()  asm volatile("cp.async.wait_group 0;" ::: "memory")

// ---------------- ldmatrix / mma.sync ---------------------------------------
__device__ __forceinline__ void ldsm4(uint32_t (&d)[4], uint32_t addr) {
    asm volatile("ldmatrix.sync.aligned.m8n8.x4.shared.b16 {%0,%1,%2,%3}, [%4];"
        : "=r"(d[0]), "=r"(d[1]), "=r"(d[2]), "=r"(d[3]) : "r"(addr));
}
__device__ __forceinline__ void mma_bf16(float (&c)[4], const uint32_t (&a)[4],
                                         uint32_t b0, uint32_t b1) {
    asm volatile("mma.sync.aligned.m16n8k16.row.col.f32.bf16.bf16.f32 "
        "{%0,%1,%2,%3}, {%4,%5,%6,%7}, {%8,%9}, {%0,%1,%2,%3};"
        : "+f"(c[0]), "+f"(c[1]), "+f"(c[2]), "+f"(c[3])
        : "r"(a[0]), "r"(a[1]), "r"(a[2]), "r"(a[3]), "r"(b0), "r"(b1));
}
__device__ __forceinline__ void mma_fp16(float (&c)[4], const uint32_t (&a)[4],
                                         uint32_t b0, uint32_t b1) {
    asm volatile("mma.sync.aligned.m16n8k16.row.col.f32.f16.f16.f32 "
        "{%0,%1,%2,%3}, {%4,%5,%6,%7}, {%8,%9}, {%0,%1,%2,%3};"
        : "+f"(c[0]), "+f"(c[1]), "+f"(c[2]), "+f"(c[3])
        : "r"(a[0]), "r"(a[1]), "r"(a[2]), "r"(a[3]), "r"(b0), "r"(b1));
}

// A-fragment address (ldmatrix x4): 16 rows starting r0, k-step ks (16 elems)
__device__ __forceinline__ uint32_t aAddr(uint32_t base, int rowbytes, int r0,
                                          int ks, int lane) {
    int row = r0 + (lane & 7) + ((lane & 8) ? 8 : 0);
    int c16 = ks * 2 + (lane >> 4);
    return base + row * rowbytes + ((uint32_t)(c16 ^ (row & 7)) << 4);
}
// B-fragment address (ldmatrix x4): 8 rows at n0, TWO k-steps (pair kp)
__device__ __forceinline__ uint32_t b4Addr(uint32_t base, int rowbytes, int n0,
                                           int kp, int lane) {
    int row = n0 + (lane & 7);
    int c16 = kp * 4 + (lane >> 3);
    return base + row * rowbytes + ((uint32_t)(c16 ^ (row & 7)) << 4);
}
__device__ __forceinline__ uint32_t swz512(uint32_t base, int row, int c16) {
    return base + row * 512 + ((uint32_t)(c16 ^ (row & 7)) << 4);
}
__device__ __forceinline__ uint32_t swz128(uint32_t base, int row, int c16) {
    return base + row * 128 + ((uint32_t)(c16 ^ (row & 7)) << 4);
}

// ---------------- scratch ---------------------------------------------------
__device__ __nv_bfloat16 g_Xh[BB * NN * CC];
__device__ __nv_bfloat16 g_Xl[BB * NN * CC];
__device__ __nv_bfloat16 g_Wht[3 * CC * DD];        // [z][n][k] transposed
__device__ __nv_bfloat16 g_Wlt[3 * CC * DD];
__device__ __half        g_Qf [BB * NN * DD];       // Q single fp16 (x 1/16)
__device__ __half        g_Khf[BB * NN * DD];       // K fp16 hi
__device__ __half        g_Klf[BB * NN * DD];       // K fp16 lo
__device__ float         g_V  [BB * NN * DD];
__device__ __half        g_Vtf[NSEG * DD * LSEG];   // per-slot V^T, single fp16
__device__ float g_O[NSEG * LSEG * DD];
__device__ float g_den[NSEG * LSEG];

__device__ __forceinline__ void slot_decode(int s, int& batch, int& posbase, int& r) {
    int w, base;
    if (s < 16)      { w = 2048; r = 1; base = 0;  }
    else if (s < 24) { w = 4096; r = 2; base = 16; }
    else             { w = 8192; r = 4; base = 24; }
    int local = s - base;
    batch = local & 3;
    posbase = (local >> 2) * w;
}

// ================= Phase 0a: split X into bf16 hi/lo ========================
__global__ __launch_bounds__(256) void split_x_kernel(const float* __restrict__ X)
{
    long e = (long)blockIdx.x * 1024 + threadIdx.x * 4;
    float4 v = *(const float4*)(X + e);
    __nv_bfloat162 h0 = __floats2bfloat162_rn(v.x, v.y);
    __nv_bfloat162 h1 = __floats2bfloat162_rn(v.z, v.w);
    __nv_bfloat162 l0 = __floats2bfloat162_rn(v.x - __bfloat162float(h0.x),
                                              v.y - __bfloat162float(h0.y));
    __nv_bfloat162 l1 = __floats2bfloat162_rn(v.z - __bfloat162float(h1.x),
                                              v.w - __bfloat162float(h1.y));
    *(__nv_bfloat162*)(g_Xh + e) = h0; *(__nv_bfloat162*)(g_Xh + e + 2) = h1;
    *(__nv_bfloat162*)(g_Xl + e) = l0; *(__nv_bfloat162*)(g_Xl + e + 2) = l1;
}

// ================= Phase 0b: transpose+split W ==============================
__global__ __launch_bounds__(256) void split_w_kernel(
    const float* __restrict__ Wq, const float* __restrict__ Wk,
    const float* __restrict__ Wv)
{
    __shared__ float T[32][33];
    const int z = blockIdx.z;
    const float* W = (z == 0) ? Wq : (z == 1) ? Wk : Wv;
    const int k0 = blockIdx.x * 32, n0 = blockIdx.y * 32;
    const int t = threadIdx.x;
    {
        int kk = t >> 3, n4 = (t & 7) << 2;
        float4 v = *(const float4*)(W + (long)(k0 + kk) * DD + n0 + n4);
        T[kk][n4] = v.x; T[kk][n4 + 1] = v.y; T[kk][n4 + 2] = v.z; T[kk][n4 + 3] = v.w;
    }
    __syncthreads();
    {
        int nn = t >> 3, k4 = (t & 7) << 2;
        float sc = (z == 0) ? 0.0625f : 1.0f;
        float v0 = T[k4][nn] * sc, v1 = T[k4 + 1][nn] * sc;
        float v2 = T[k4 + 2][nn] * sc, v3 = T[k4 + 3][nn] * sc;
        __nv_bfloat162 h0 = __floats2bfloat162_rn(v0, v1);
        __nv_bfloat162 h1 = __floats2bfloat162_rn(v2, v3);
        __nv_bfloat162 l0 = __floats2bfloat162_rn(v0 - __bfloat162float(h0.x),
                                                  v1 - __bfloat162float(h0.y));
        __nv_bfloat162 l1 = __floats2bfloat162_rn(v2 - __bfloat162float(h1.x),
                                                  v3 - __bfloat162float(h1.y));
        long off = (long)z * (CC * DD) + (long)(n0 + nn) * CC + k0 + k4;
        *(__nv_bfloat162*)(g_Wht + off) = h0; *(__nv_bfloat162*)(g_Wht + off + 2) = h1;
        *(__nv_bfloat162*)(g_Wlt + off) = l0; *(__nv_bfloat162*)(g_Wlt + off + 2) = l1;
    }
}

// ================= Phase 1: QKV projection via mma.sync =====================
#define GX_H 0
#define GX_L 32768
#define GW_H 65536
#define GW_L 98304
#define QKV_SMEM 131072

__global__ __launch_bounds__(256, 1) void qkv_mma_kernel()
{
    extern __shared__ char smem[];
    const uint32_t sb = smem_to_u32(smem);
    const int t = threadIdx.x, lane = t & 31, wid = t >> 5;
    const int m0 = blockIdx.x * 128, n0 = blockIdx.y * 128, z = blockIdx.z;
    const __nv_bfloat16* Wh = g_Wht + (long)z * (CC * DD);
    const __nv_bfloat16* Wl = g_Wlt + (long)z * (CC * DD);

    auto loadslab = [&](int s, int buf) {
        int k0 = s * 64;
        uint32_t bo = (uint32_t)buf * 16384;
#pragma unroll
        for (int i = 0; i < 4; i++) {
            int e = t + i * 256;
            int row = e >> 3, c16 = e & 7;
            long xs = (long)(m0 + row) * CC + k0 + c16 * 8;
            cp16(swz128(sb + GX_H + bo, row, c16), g_Xh + xs);
            cp16(swz128(sb + GX_L + bo, row, c16), g_Xl + xs);
            long ws = (long)(n0 + row) * CC + k0 + c16 * 8;
            cp16(swz128(sb + GW_H + bo, row, c16), Wh + ws);
            cp16(swz128(sb + GW_L + bo, row, c16), Wl + ws);
        }
    };

    float acc[16][4];
#pragma unroll
    for (int nt = 0; nt < 16; nt++)
#pragma unroll
        for (int c = 0; c < 4; c++) acc[nt][c] = 0.f;

    loadslab(0, 0); CP_COMMIT();
    for (int s = 0; s < 4; s++) {
        if (s < 3) { loadslab(s + 1, (s + 1) & 1); CP_COMMIT(); CP_WAIT1(); }
        else CP_WAIT0();
        __syncthreads();
        uint32_t bo = (uint32_t)(s & 1) * 16384;
#pragma unroll
        for (int kp = 0; kp < 2; kp++) {
            uint32_t ah0[4], ah1[4], al0[4], al1[4];
            ldsm4(ah0, aAddr(sb + GX_H + bo, 128, wid * 16, 2 * kp,     lane));
            ldsm4(ah1, aAddr(sb + GX_H + bo, 128, wid * 16, 2 * kp + 1, lane));
            ldsm4(al0, aAddr(sb + GX_L + bo, 128, wid * 16, 2 * kp,     lane));
            ldsm4(al1, aAddr(sb + GX_L + bo, 128, wid * 16, 2 * kp + 1, lane));
#pragma unroll
            for (int nt = 0; nt < 16; nt++) {
                uint32_t bh[4], bl[4];
                ldsm4(bh, b4Addr(sb + GW_H + bo, 128, nt * 8, kp, lane));
                ldsm4(bl, b4Addr(sb + GW_L + bo, 128, nt * 8, kp, lane));
                mma_bf16(acc[nt], ah0, bh[0], bh[1]);
                mma_bf16(acc[nt], ah0, bl[0], bl[1]);
                mma_bf16(acc[nt], al0, bh[0], bh[1]);
                mma_bf16(acc[nt], ah1, bh[2], bh[3]);
                mma_bf16(acc[nt], ah1, bl[2], bl[3]);
                mma_bf16(acc[nt], al1, bh[2], bh[3]);
            }
        }
        __syncthreads();
    }

    const int g = lane >> 2, cpair = 2 * (lane & 3);
#pragma unroll
    for (int nt = 0; nt < 16; nt++) {
        long r0 = (long)(m0 + wid * 16 + g) * DD + n0 + nt * 8 + cpair;
        long r1 = r0 + 8 * DD;
        if (z == 2) {
            *(float2*)(g_V + r0) = make_float2(acc[nt][0], acc[nt][1]);
            *(float2*)(g_V + r1) = make_float2(acc[nt][2], acc[nt][3]);
        } else if (z == 0) {
            *(__half2*)(g_Qf + r0) = __floats2half2_rn(acc[nt][0], acc[nt][1]);
            *(__half2*)(g_Qf + r1) = __floats2half2_rn(acc[nt][2], acc[nt][3]);
        } else {
            __half2 h0 = __floats2half2_rn(acc[nt][0], acc[nt][1]);
            __half2 l0 = __floats2half2_rn(acc[nt][0] - __half2float(h0.x),
                                           acc[nt][1] - __half2float(h0.y));
            __half2 h1 = __floats2half2_rn(acc[nt][2], acc[nt][3]);
            __half2 l1 = __floats2half2_rn(acc[nt][2] - __half2float(h1.x),
                                           acc[nt][3] - __half2float(h1.y));
            *(__half2*)(g_Khf + r0) = h0; *(__half2*)(g_Klf + r0) = l0;
            *(__half2*)(g_Khf + r1) = h1; *(__half2*)(g_Klf + r1) = l1;
        }
    }
}

// ================= Phase 1b: per-slot V^T gather (single fp16) ==============
__global__ __launch_bounds__(256) void transpose_v_kernel()
{
    __shared__ float T[32][36];
    const int s = blockIdx.z, jt = blockIdx.x, dt = blockIdx.y;
    int batch, posbase, r;
    slot_decode(s, batch, posbase, r);

    const int t = threadIdx.x;
    {
        int jl = t >> 3, dq = (t & 7) << 2;
        int pos = posbase + (jt * 32 + jl) * r;
        float4 v = *(const float4*)(g_V + ((long)batch * NN + pos) * DD + dt * 32 + dq);
        T[jl][dq] = v.x; T[jl][dq + 1] = v.y; T[jl][dq + 2] = v.z; T[jl][dq + 3] = v.w;
    }
    __syncthreads();
    {
        int dl = t >> 3, jq = (t & 7) << 2;
        __half2 h0 = __floats2half2_rn(T[jq][dl], T[jq + 1][dl]);
        __half2 h1 = __floats2half2_rn(T[jq + 2][dl], T[jq + 3][dl]);
        long off = ((long)s * DD + dt * 32 + dl) * LSEG + jt * 32 + jq;
        *(__half2*)(g_Vtf + off) = h0;
        *(__half2*)(g_Vtf + off + 2) = h1;
    }
}

// ================= Phase 2: mma.sync fp16 causal attention ==================
// S: Qf(fp16) x (Kh + Kl)(fp16), 2 terms.  PV: P(fp16) x V(fp16), 1 term.
#define OQ  0
#define OKH 32768
#define OKL 65536
#define OVH 98304
#define OPH 131072
#define OLS 139264
#define SM_TOTAL (OLS + 512)

__global__ __launch_bounds__(256, 1) void attn_kernel()
{
    extern __shared__ char smem[];
    const uint32_t sb = smem_to_u32(smem);
    float* lsum2 = (float*)(smem + OLS);

    const int t = threadIdx.x, lane = t & 31, wid = t >> 5;
    const int qt = 31 - (int)blockIdx.x;          // heavy tiles first
    const int s  = blockIdx.y;
    int batch, posbase, r;
    slot_decode(s, batch, posbase, r);
    const long qkvoff = (long)batch * (NN * DD);

    auto issueK = [&](int kt) {
#pragma unroll
        for (int sp = 0; sp < 2; sp++)
#pragma unroll
            for (int i = 0; i < 8; i++) {
                int e = t + i * 256;
                int key = e >> 5, c16 = e & 31;
                cp16(swz512(sb + (sp ? OKL : OKH), key, c16),
                     (const void*)((sp ? g_Klf : g_Khf) + qkvoff +
                     ((long)(posbase + (kt * 64 + key) * r)) * DD + c16 * 8));
            }
    };
    auto issueV = [&](int kt) {
#pragma unroll
        for (int i = 0; i < 8; i++) {
            int e = t + i * 256;
            int d = e >> 3, c16 = e & 7;
            cp16(swz128(sb + OVH, d, c16),
                 (const void*)(g_Vtf + (long)s * DD * LSEG +
                               (long)d * LSEG + kt * 64 + c16 * 8));
        }
    };

    // prologue: Q tile + K(0)
    {
#pragma unroll
        for (int i = 0; i < 8; i++) {
            int e = t + i * 256;
            int row = e >> 5, c16 = e & 31;
            cp16(swz512(sb + OQ, row, c16),
                 (const void*)(g_Qf + qkvoff +
                 ((long)(posbase + (qt * 64 + row) * r)) * DD + c16 * 8));
        }
        CP_COMMIT();
        issueK(0); CP_COMMIT();
    }

    const int g = lane >> 2, cpair = 2 * (lane & 3);
    const int wq = wid & 3, wk = wid >> 2;
    float accd[4][4][4];
#pragma unroll
    for (int mt = 0; mt < 4; mt++)
#pragma unroll
        for (int nt = 0; nt < 4; nt++)
#pragma unroll
            for (int c = 0; c < 4; c++) accd[mt][nt][c] = 0.f;
    float rs0 = 0.f, rs1 = 0.f;

    for (int kt = 0; kt <= qt; kt++) {
        __syncthreads();                          // V buf free (prev PV done)
        issueV(kt); CP_COMMIT();
        CP_WAIT1();                               // Q + K(kt) landed
        __syncthreads();

        // ---- S = Q K^T: warp does 16q x 32k, 2 fp16 terms -----------------
        float sacc[4][4];
#pragma unroll
        for (int nt = 0; nt < 4; nt++)
#pragma unroll
            for (int c = 0; c < 4; c++) sacc[nt][c] = 0.f;
#pragma unroll 2
        for (int kp = 0; kp < 8; kp++) {
            uint32_t ah0[4], ah1[4];
            ldsm4(ah0, aAddr(sb + OQ, 512, wq * 16, 2 * kp,     lane));
            ldsm4(ah1, aAddr(sb + OQ, 512, wq * 16, 2 * kp + 1, lane));
#pragma unroll
            for (int nt = 0; nt < 4; nt++) {
                uint32_t bh[4], bl[4];
                ldsm4(bh, b4Addr(sb + OKH, 512, wk * 32 + nt * 8, kp, lane));
                ldsm4(bl, b4Addr(sb + OKL, 512, wk * 32 + nt * 8, kp, lane));
                mma_fp16(sacc[nt], ah0, bh[0], bh[1]);
                mma_fp16(sacc[nt], ah0, bl[0], bl[1]);
                mma_fp16(sacc[nt], ah1, bh[2], bh[3]);
                mma_fp16(sacc[nt], ah1, bl[2], bl[3]);
            }
        }

        // ---- softmax: mask, exp, row-sum, pack P (single fp16) -------------
        const int prow0 = wq * 16 + g, prow1 = prow0 + 8;
        const int qrow0 = qt * 64 + prow0, qrow1 = qt * 64 + prow1;
#pragma unroll
        for (int nt = 0; nt < 4; nt++) {
            int kcol = wk * 32 + nt * 8 + cpair;
            int kg = kt * 64 + kcol;
            float p00 = (kg     <= qrow0) ? __expf(sacc[nt][0]) : 0.f;
            float p01 = (kg + 1 <= qrow0) ? __expf(sacc[nt][1]) : 0.f;
            float p10 = (kg     <= qrow1) ? __expf(sacc[nt][2]) : 0.f;
            float p11 = (kg + 1 <= qrow1) ? __expf(sacc[nt][3]) : 0.f;
            rs0 += p00 + p01;
            rs1 += p10 + p11;
            __half2 h0 = __floats2half2_rn(p00, p01);
            __half2 h1 = __floats2half2_rn(p10, p11);
            uint32_t ob0 = prow0 * 128 + ((uint32_t)((kcol >> 3) ^ (prow0 & 7)) << 4)
                         + (kcol & 7) * 2;
            uint32_t ob1 = prow1 * 128 + ((uint32_t)((kcol >> 3) ^ (prow1 & 7)) << 4)
                         + (kcol & 7) * 2;
            *(__half2*)(smem + OPH + ob0) = h0;
            *(__half2*)(smem + OPH + ob1) = h1;
        }
        __syncthreads();                          // P visible; K buf free

        // ---- prefetch next K (overlaps PV), then wait V --------------------
        if (kt < qt) { issueK(kt + 1); CP_COMMIT(); CP_WAIT1(); }
        else CP_WAIT0();
        __syncthreads();                          // V visible to all

        // ---- D += P V: warp owns 32 d-cols; single fp16 term ---------------
        const int n0 = wid * 32;
#pragma unroll
        for (int kp = 0; kp < 2; kp++) {
            uint32_t bh[4][4];
#pragma unroll
            for (int nt = 0; nt < 4; nt++)
                ldsm4(bh[nt], b4Addr(sb + OVH, 128, n0 + nt * 8, kp, lane));
#pragma unroll
            for (int mt = 0; mt < 4; mt++) {
                uint32_t ah0[4], ah1[4];
                ldsm4(ah0, aAddr(sb + OPH, 128, mt * 16, 2 * kp,     lane));
                ldsm4(ah1, aAddr(sb + OPH, 128, mt * 16, 2 * kp + 1, lane));
#pragma unroll
                for (int nt = 0; nt < 4; nt++) {
                    mma_fp16(accd[mt][nt], ah0, bh[nt][0], bh[nt][1]);
                    mma_fp16(accd[mt][nt], ah1, bh[nt][2], bh[nt][3]);
                }
            }
        }
    }

    // ---- epilogue ---------------------------------------------------------
    rs0 += __shfl_xor_sync(0xffffffffu, rs0, 1);
    rs0 += __shfl_xor_sync(0xffffffffu, rs0, 2);
    rs1 += __shfl_xor_sync(0xffffffffu, rs1, 1);
    rs1 += __shfl_xor_sync(0xffffffffu, rs1, 2);
    if ((lane & 3) == 0) {
        lsum2[wk * 64 + wq * 16 + g]     = rs0;
        lsum2[wk * 64 + wq * 16 + g + 8] = rs1;
    }
    __syncthreads();

#pragma unroll
    for (int mt = 0; mt < 4; mt++) {
        int lr0 = mt * 16 + g, lr1 = lr0 + 8;
        float inv0 = 1.0f / (lsum2[lr0] + lsum2[64 + lr0]);
        float inv1 = 1.0f / (lsum2[lr1] + lsum2[64 + lr1]);
        long ro0 = (long)(s * LSEG + qt * 64 + lr0) * DD;
        long ro1 = (long)(s * LSEG + qt * 64 + lr1) * DD;
#pragma unroll
        for (int nt = 0; nt < 4; nt++) {
            int col = wid * 32 + nt * 8 + cpair;
            *(float2*)(g_O + ro0 + col) =
                make_float2(accd[mt][nt][0] * inv0, accd[mt][nt][1] * inv0);
            *(float2*)(g_O + ro1 + col) =
                make_float2(accd[mt][nt][2] * inv1, accd[mt][nt][3] * inv1);
        }
    }
    if (t < 64)
        g_den[s * LSEG + qt * 64 + t] = lsum2[t] + lsum2[64 + t];
}

// ================= Phase 3: combine (gather) ================================
__global__ __launch_bounds__(256) void combine_kernel(float* __restrict__ out)
{
    const int token = blockIdx.x * 4 + (threadIdx.x >> 6);
    const int lane  = threadIdx.x & 63;
    const int b = token >> 13, p = token & 8191;

    const int slot0 = (p >> 11) * 4 + b, j0 = p & 2047;
    float d0 = g_den[slot0 * LSEG + j0];
    float sum = d0;
    int slot1 = -1, j1 = 0, slot2 = -1, j2 = 0;
    float d1 = 0.f, d2 = 0.f;
    if ((p & 1) == 0) {
        slot1 = 16 + (p >> 12) * 4 + b; j1 = (p & 4095) >> 1;
        d1 = g_den[slot1 * LSEG + j1]; sum += d1;
    }
    if ((p & 3) == 0) {
        slot2 = 24 + b; j2 = p >> 2;
        d2 = g_den[slot2 * LSEG + j2]; sum += d2;
    }
    const float inv = 1.0f / sum;
    const int c = lane << 2;

    float4 o0 = *(const float4*)(g_O + ((long)slot0 * LSEG + j0) * DD + c);
    float a0 = d0 * inv;
    float4 res;
    res.x = o0.x * a0; res.y = o0.y * a0; res.z = o0.z * a0; res.w = o0.w * a0;
    if (slot1 >= 0) {
        float4 o1 = *(const float4*)(g_O + ((long)slot1 * LSEG + j1) * DD + c);
        float a1 = d1 * inv;
        res.x = fmaf(o1.x, a1, res.x); res.y = fmaf(o1.y, a1, res.y);
        res.z = fmaf(o1.z, a1, res.z); res.w = fmaf(o1.w, a1, res.w);
    }
    if (slot2 >= 0) {
        float4 o2v = *(const float4*)(g_O + ((long)slot2 * LSEG + j2) * DD + c);
        float a2 = d2 * inv;
        res.x = fmaf(o2v.x, a2, res.x); res.y = fmaf(o2v.y, a2, res.y);
        res.z = fmaf(o2v.z, a2, res.z); res.w = fmaf(o2v.w, a2, res.w);
    }
    *(float4*)(out + ((long)b * NN + p) * DD + c) = res;
}

// ================= launch ====================================================
extern "C" void kernel_launch(void* const* d_in, const int* in_sizes, int n_in,
                              void* d_out, int out_size)
{
    (void)in_sizes; (void)n_in; (void)out_size;
    const float* x  = (const float*)d_in[0];
    const float* Wq = (const float*)d_in[1];
    const float* Wk = (const float*)d_in[2];
    const float* Wv = (const float*)d_in[3];

    cudaFuncSetAttribute(qkv_mma_kernel, cudaFuncAttributeMaxDynamicSharedMemorySize,
                         QKV_SMEM);
    cudaFuncSetAttribute(attn_kernel, cudaFuncAttributeMaxDynamicSharedMemorySize,
                         SM_TOTAL);

    split_x_kernel<<<8192, 256>>>(x);
    split_w_kernel<<<dim3(8, 8, 3), 256>>>(Wq, Wk, Wv);
    qkv_mma_kernel<<<dim3(256, 2, 3), 256, QKV_SMEM>>>();
    transpose_v_kernel<<<dim3(64, 8, 28), 256>>>();
    attn_kernel<<<dim3(32, 28), 256, SM_TOTAL>>>();
    combine_kernel<<<8192, 256>>>((float*)d_out);
}

// round 11
// speedup vs baseline: 6.0854x; 1.3248x over previous
#include <cuda_runtime.h>
#include <cuda_bf16.h>
#include <cuda_fp16.h>
#include <stdint.h>
#include <math.h>

#define BB   4
#define NN   8192
#define CC   256
#define DD   256
#define LSEG 2048
#define NSEG 28

// ---------------- cp.async helpers -----------------------------------------
__device__ __forceinline__ uint32_t smem_to_u32(const void* p) {
    uint32_t a;
    asm("{ .reg .u64 t; cvta.to.shared.u64 t, %1; cvt.u32.u64 %0, t; }"
        : "=r"(a) : "l"(p));
    return a;
}
__device__ __forceinline__ void cp16(uint32_t dst, const void* src) {
    asm volatile("cp.async.cg.shared.global [%0], [%1], 16;" :: "r"(dst), "l"(src) : "memory");
}
#define CP_COMMIT() asm volatile("cp.async.commit_group;" ::: "memory")
#define CP_WAIT1()  asm volatile("cp.async.wait_group 1;" ::: "memory")
#define CP_WAIT0()  asm volatile("cp.async.wait_group 0;" ::: "memory")

// ---------------- ldmatrix / mma.sync ---------------------------------------
__device__ __forceinline__ void ldsm4(uint32_t (&d)[4], uint32_t addr) {
    asm volatile("ldmatrix.sync.aligned.m8n8.x4.shared.b16 {%0,%1,%2,%3}, [%4];"
        : "=r"(d[0]), "=r"(d[1]), "=r"(d[2]), "=r"(d[3]) : "r"(addr));
}
__device__ __forceinline__ void mma_fp16(float (&c)[4], const uint32_t (&a)[4],
                                         uint32_t b0, uint32_t b1) {
    asm volatile("mma.sync.aligned.m16n8k16.row.col.f32.f16.f16.f32 "
        "{%0,%1,%2,%3}, {%4,%5,%6,%7}, {%8,%9}, {%0,%1,%2,%3};"
        : "+f"(c[0]), "+f"(c[1]), "+f"(c[2]), "+f"(c[3])
        : "r"(a[0]), "r"(a[1]), "r"(a[2]), "r"(a[3]), "r"(b0), "r"(b1));
}

// A-fragment address (ldmatrix x4): 16 rows starting r0, k-step ks (16 elems)
__device__ __forceinline__ uint32_t aAddr(uint32_t base, int rowbytes, int r0,
                                          int ks, int lane) {
    int row = r0 + (lane & 7) + ((lane & 8) ? 8 : 0);
    int c16 = ks * 2 + (lane >> 4);
    return base + row * rowbytes + ((uint32_t)(c16 ^ (row & 7)) << 4);
}
// B-fragment address (ldmatrix x4): 8 rows at n0, TWO k-steps (pair kp)
__device__ __forceinline__ uint32_t b4Addr(uint32_t base, int rowbytes, int n0,
                                           int kp, int lane) {
    int row = n0 + (lane & 7);
    int c16 = kp * 4 + (lane >> 3);
    return base + row * rowbytes + ((uint32_t)(c16 ^ (row & 7)) << 4);
}
__device__ __forceinline__ uint32_t swz512(uint32_t base, int row, int c16) {
    return base + row * 512 + ((uint32_t)(c16 ^ (row & 7)) << 4);
}
__device__ __forceinline__ uint32_t swz128(uint32_t base, int row, int c16) {
    return base + row * 128 + ((uint32_t)(c16 ^ (row & 7)) << 4);
}

// ---------------- scratch ---------------------------------------------------
__device__ __half        g_Xf [BB * NN * CC];       // X single fp16
__device__ __half        g_Whf[3 * CC * DD];        // [z][n][k] transposed, fp16 hi
__device__ __half        g_Wlf[3 * CC * DD];        // fp16 lo
__device__ __half        g_Qf [BB * NN * DD];       // Q single fp16 (x 1/16)
__device__ __half        g_Kf [BB * NN * DD];       // K single fp16
__device__ float         g_V  [BB * NN * DD];
__device__ __half        g_Vtf[NSEG * DD * LSEG];   // per-slot V^T, single fp16
__device__ float g_O[NSEG * LSEG * DD];
__device__ float g_den[NSEG * LSEG];

__device__ __forceinline__ void slot_decode(int s, int& batch, int& posbase, int& r) {
    int w, base;
    if (s < 16)      { w = 2048; r = 1; base = 0;  }
    else if (s < 24) { w = 4096; r = 2; base = 16; }
    else             { w = 8192; r = 4; base = 24; }
    int local = s - base;
    batch = local & 3;
    posbase = (local >> 2) * w;
}

// ================= Phase 0a: convert X to single fp16 =======================
__global__ __launch_bounds__(256) void split_x_kernel(const float* __restrict__ X)
{
    long e = (long)blockIdx.x * 1024 + threadIdx.x * 4;
    float4 v = *(const float4*)(X + e);
    *(__half2*)(g_Xf + e)     = __floats2half2_rn(v.x, v.y);
    *(__half2*)(g_Xf + e + 2) = __floats2half2_rn(v.z, v.w);
}

// ================= Phase 0b: transpose+split W (fp16 hi/lo) =================
__global__ __launch_bounds__(256) void split_w_kernel(
    const float* __restrict__ Wq, const float* __restrict__ Wk,
    const float* __restrict__ Wv)
{
    __shared__ float T[32][33];
    const int z = blockIdx.z;
    const float* W = (z == 0) ? Wq : (z == 1) ? Wk : Wv;
    const int k0 = blockIdx.x * 32, n0 = blockIdx.y * 32;
    const int t = threadIdx.x;
    {
        int kk = t >> 3, n4 = (t & 7) << 2;
        float4 v = *(const float4*)(W + (long)(k0 + kk) * DD + n0 + n4);
        T[kk][n4] = v.x; T[kk][n4 + 1] = v.y; T[kk][n4 + 2] = v.z; T[kk][n4 + 3] = v.w;
    }
    __syncthreads();
    {
        int nn = t >> 3, k4 = (t & 7) << 2;
        float sc = (z == 0) ? 0.0625f : 1.0f;
        float v0 = T[k4][nn] * sc, v1 = T[k4 + 1][nn] * sc;
        float v2 = T[k4 + 2][nn] * sc, v3 = T[k4 + 3][nn] * sc;
        __half2 h0 = __floats2half2_rn(v0, v1);
        __half2 h1 = __floats2half2_rn(v2, v3);
        __half2 l0 = __floats2half2_rn(v0 - __half2float(h0.x),
                                       v1 - __half2float(h0.y));
        __half2 l1 = __floats2half2_rn(v2 - __half2float(h1.x),
                                       v3 - __half2float(h1.y));
        long off = (long)z * (CC * DD) + (long)(n0 + nn) * CC + k0 + k4;
        *(__half2*)(g_Whf + off) = h0; *(__half2*)(g_Whf + off + 2) = h1;
        *(__half2*)(g_Wlf + off) = l0; *(__half2*)(g_Wlf + off + 2) = l1;
    }
}

// ================= Phase 1: QKV projection via mma.sync =====================
// X single fp16 x W (fp16 hi+lo): 2 terms (W split exact).
#define GX   0
#define GW_H 32768
#define GW_L 65536
#define QKV_SMEM 98304

__global__ __launch_bounds__(256, 1) void qkv_mma_kernel()
{
    extern __shared__ char smem[];
    const uint32_t sb = smem_to_u32(smem);
    const int t = threadIdx.x, lane = t & 31, wid = t >> 5;
    const int m0 = blockIdx.x * 128, n0 = blockIdx.y * 128, z = blockIdx.z;
    const __half* Wh = g_Whf + (long)z * (CC * DD);
    const __half* Wl = g_Wlf + (long)z * (CC * DD);

    auto loadslab = [&](int s, int buf) {
        int k0 = s * 64;
        uint32_t bo = (uint32_t)buf * 16384;
#pragma unroll
        for (int i = 0; i < 4; i++) {
            int e = t + i * 256;
            int row = e >> 3, c16 = e & 7;
            long xs = (long)(m0 + row) * CC + k0 + c16 * 8;
            cp16(swz128(sb + GX + bo, row, c16), (const void*)(g_Xf + xs));
            long ws = (long)(n0 + row) * CC + k0 + c16 * 8;
            cp16(swz128(sb + GW_H + bo, row, c16), (const void*)(Wh + ws));
            cp16(swz128(sb + GW_L + bo, row, c16), (const void*)(Wl + ws));
        }
    };

    float acc[16][4];
#pragma unroll
    for (int nt = 0; nt < 16; nt++)
#pragma unroll
        for (int c = 0; c < 4; c++) acc[nt][c] = 0.f;

    loadslab(0, 0); CP_COMMIT();
    for (int s = 0; s < 4; s++) {
        if (s < 3) { loadslab(s + 1, (s + 1) & 1); CP_COMMIT(); CP_WAIT1(); }
        else CP_WAIT0();
        __syncthreads();
        uint32_t bo = (uint32_t)(s & 1) * 16384;
#pragma unroll
        for (int kp = 0; kp < 2; kp++) {
            uint32_t af0[4], af1[4];
            ldsm4(af0, aAddr(sb + GX + bo, 128, wid * 16, 2 * kp,     lane));
            ldsm4(af1, aAddr(sb + GX + bo, 128, wid * 16, 2 * kp + 1, lane));
#pragma unroll
            for (int nt = 0; nt < 16; nt++) {
                uint32_t bh[4], bl[4];
                ldsm4(bh, b4Addr(sb + GW_H + bo, 128, nt * 8, kp, lane));
                ldsm4(bl, b4Addr(sb + GW_L + bo, 128, nt * 8, kp, lane));
                mma_fp16(acc[nt], af0, bh[0], bh[1]);
                mma_fp16(acc[nt], af0, bl[0], bl[1]);
                mma_fp16(acc[nt], af1, bh[2], bh[3]);
                mma_fp16(acc[nt], af1, bl[2], bl[3]);
            }
        }
        __syncthreads();
    }

    const int g = lane >> 2, cpair = 2 * (lane & 3);
#pragma unroll
    for (int nt = 0; nt < 16; nt++) {
        long r0 = (long)(m0 + wid * 16 + g) * DD + n0 + nt * 8 + cpair;
        long r1 = r0 + 8 * DD;
        if (z == 2) {
            *(float2*)(g_V + r0) = make_float2(acc[nt][0], acc[nt][1]);
            *(float2*)(g_V + r1) = make_float2(acc[nt][2], acc[nt][3]);
        } else {
            __half* dst = (z == 0) ? g_Qf : g_Kf;
            *(__half2*)(dst + r0) = __floats2half2_rn(acc[nt][0], acc[nt][1]);
            *(__half2*)(dst + r1) = __floats2half2_rn(acc[nt][2], acc[nt][3]);
        }
    }
}

// ================= Phase 1b: per-slot V^T gather (single fp16) ==============
__global__ __launch_bounds__(256) void transpose_v_kernel()
{
    __shared__ float T[32][36];
    const int s = blockIdx.z, jt = blockIdx.x, dt = blockIdx.y;
    int batch, posbase, r;
    slot_decode(s, batch, posbase, r);

    const int t = threadIdx.x;
    {
        int jl = t >> 3, dq = (t & 7) << 2;
        int pos = posbase + (jt * 32 + jl) * r;
        float4 v = *(const float4*)(g_V + ((long)batch * NN + pos) * DD + dt * 32 + dq);
        T[jl][dq] = v.x; T[jl][dq + 1] = v.y; T[jl][dq + 2] = v.z; T[jl][dq + 3] = v.w;
    }
    __syncthreads();
    {
        int dl = t >> 3, jq = (t & 7) << 2;
        __half2 h0 = __floats2half2_rn(T[jq][dl], T[jq + 1][dl]);
        __half2 h1 = __floats2half2_rn(T[jq + 2][dl], T[jq + 3][dl]);
        long off = ((long)s * DD + dt * 32 + dl) * LSEG + jt * 32 + jq;
        *(__half2*)(g_Vtf + off) = h0;
        *(__half2*)(g_Vtf + off + 2) = h1;
    }
}

// ================= Phase 2: mma.sync fp16 causal attention ==================
// S: Qf x Kf, single fp16 term.  PV: P(fp16) x V(fp16), single term.
#define OQ  0
#define OK  32768
#define OV  65536
#define OP  98304
#define OLS 106496
#define SM_TOTAL (OLS + 512)

__global__ __launch_bounds__(256, 1) void attn_kernel()
{
    extern __shared__ char smem[];
    const uint32_t sb = smem_to_u32(smem);
    float* lsum2 = (float*)(smem + OLS);

    const int t = threadIdx.x, lane = t & 31, wid = t >> 5;
    const int qt = 31 - (int)blockIdx.x;          // heavy tiles first
    const int s  = blockIdx.y;
    int batch, posbase, r;
    slot_decode(s, batch, posbase, r);
    const long qkvoff = (long)batch * (NN * DD);

    auto issueK = [&](int kt) {
#pragma unroll
        for (int i = 0; i < 8; i++) {
            int e = t + i * 256;
            int key = e >> 5, c16 = e & 31;
            cp16(swz512(sb + OK, key, c16),
                 (const void*)(g_Kf + qkvoff +
                 ((long)(posbase + (kt * 64 + key) * r)) * DD + c16 * 8));
        }
    };
    auto issueV = [&](int kt) {
#pragma unroll
        for (int i = 0; i < 8; i++) {
            int e = t + i * 256;
            int d = e >> 3, c16 = e & 7;
            cp16(swz128(sb + OV, d, c16),
                 (const void*)(g_Vtf + (long)s * DD * LSEG +
                               (long)d * LSEG + kt * 64 + c16 * 8));
        }
    };

    // prologue: Q tile + K(0)
    {
#pragma unroll
        for (int i = 0; i < 8; i++) {
            int e = t + i * 256;
            int row = e >> 5, c16 = e & 31;
            cp16(swz512(sb + OQ, row, c16),
                 (const void*)(g_Qf + qkvoff +
                 ((long)(posbase + (qt * 64 + row) * r)) * DD + c16 * 8));
        }
        CP_COMMIT();
        issueK(0); CP_COMMIT();
    }

    const int g = lane >> 2, cpair = 2 * (lane & 3);
    const int wq = wid & 3, wk = wid >> 2;
    float accd[4][4][4];
#pragma unroll
    for (int mt = 0; mt < 4; mt++)
#pragma unroll
        for (int nt = 0; nt < 4; nt++)
#pragma unroll
            for (int c = 0; c < 4; c++) accd[mt][nt][c] = 0.f;
    float rs0 = 0.f, rs1 = 0.f;

    for (int kt = 0; kt <= qt; kt++) {
        __syncthreads();                          // V buf free (prev PV done)
        issueV(kt); CP_COMMIT();
        CP_WAIT1();                               // Q + K(kt) landed
        __syncthreads();

        // ---- S = Q K^T: warp does 16q x 32k, single fp16 term -------------
        float sacc[4][4];
#pragma unroll
        for (int nt = 0; nt < 4; nt++)
#pragma unroll
            for (int c = 0; c < 4; c++) sacc[nt][c] = 0.f;
#pragma unroll 4
        for (int kp = 0; kp < 8; kp++) {
            uint32_t ah0[4], ah1[4];
            ldsm4(ah0, aAddr(sb + OQ, 512, wq * 16, 2 * kp,     lane));
            ldsm4(ah1, aAddr(sb + OQ, 512, wq * 16, 2 * kp + 1, lane));
#pragma unroll
            for (int nt = 0; nt < 4; nt++) {
                uint32_t bh[4];
                ldsm4(bh, b4Addr(sb + OK, 512, wk * 32 + nt * 8, kp, lane));
                mma_fp16(sacc[nt], ah0, bh[0], bh[1]);
                mma_fp16(sacc[nt], ah1, bh[2], bh[3]);
            }
        }

        // ---- softmax: mask, exp, row-sum, pack P (single fp16) -------------
        const int prow0 = wq * 16 + g, prow1 = prow0 + 8;
        const int qrow0 = qt * 64 + prow0, qrow1 = qt * 64 + prow1;
#pragma unroll
        for (int nt = 0; nt < 4; nt++) {
            int kcol = wk * 32 + nt * 8 + cpair;
            int kg = kt * 64 + kcol;
            float p00 = (kg     <= qrow0) ? __expf(sacc[nt][0]) : 0.f;
            float p01 = (kg + 1 <= qrow0) ? __expf(sacc[nt][1]) : 0.f;
            float p10 = (kg     <= qrow1) ? __expf(sacc[nt][2]) : 0.f;
            float p11 = (kg + 1 <= qrow1) ? __expf(sacc[nt][3]) : 0.f;
            rs0 += p00 + p01;
            rs1 += p10 + p11;
            __half2 h0 = __floats2half2_rn(p00, p01);
            __half2 h1 = __floats2half2_rn(p10, p11);
            uint32_t ob0 = prow0 * 128 + ((uint32_t)((kcol >> 3) ^ (prow0 & 7)) << 4)
                         + (kcol & 7) * 2;
            uint32_t ob1 = prow1 * 128 + ((uint32_t)((kcol >> 3) ^ (prow1 & 7)) << 4)
                         + (kcol & 7) * 2;
            *(__half2*)(smem + OP + ob0) = h0;
            *(__half2*)(smem + OP + ob1) = h1;
        }
        __syncthreads();                          // P visible; K buf free

        // ---- prefetch next K (overlaps PV), then wait V --------------------
        if (kt < qt) { issueK(kt + 1); CP_COMMIT(); CP_WAIT1(); }
        else CP_WAIT0();
        __syncthreads();                          // V visible to all

        // ---- D += P V: warp owns 32 d-cols; single fp16 term ---------------
        const int n0 = wid * 32;
#pragma unroll
        for (int kp = 0; kp < 2; kp++) {
            uint32_t bh[4][4];
#pragma unroll
            for (int nt = 0; nt < 4; nt++)
                ldsm4(bh[nt], b4Addr(sb + OV, 128, n0 + nt * 8, kp, lane));
#pragma unroll
            for (int mt = 0; mt < 4; mt++) {
                uint32_t ah0[4], ah1[4];
                ldsm4(ah0, aAddr(sb + OP, 128, mt * 16, 2 * kp,     lane));
                ldsm4(ah1, aAddr(sb + OP, 128, mt * 16, 2 * kp + 1, lane));
#pragma unroll
                for (int nt = 0; nt < 4; nt++) {
                    mma_fp16(accd[mt][nt], ah0, bh[nt][0], bh[nt][1]);
                    mma_fp16(accd[mt][nt], ah1, bh[nt][2], bh[nt][3]);
                }
            }
        }
    }

    // ---- epilogue ---------------------------------------------------------
    rs0 += __shfl_xor_sync(0xffffffffu, rs0, 1);
    rs0 += __shfl_xor_sync(0xffffffffu, rs0, 2);
    rs1 += __shfl_xor_sync(0xffffffffu, rs1, 1);
    rs1 += __shfl_xor_sync(0xffffffffu, rs1, 2);
    if ((lane & 3) == 0) {
        lsum2[wk * 64 + wq * 16 + g]     = rs0;
        lsum2[wk * 64 + wq * 16 + g + 8] = rs1;
    }
    __syncthreads();

#pragma unroll
    for (int mt = 0; mt < 4; mt++) {
        int lr0 = mt * 16 + g, lr1 = lr0 + 8;
        float inv0 = 1.0f / (lsum2[lr0] + lsum2[64 + lr0]);
        float inv1 = 1.0f / (lsum2[lr1] + lsum2[64 + lr1]);
        long ro0 = (long)(s * LSEG + qt * 64 + lr0) * DD;
        long ro1 = (long)(s * LSEG + qt * 64 + lr1) * DD;
#pragma unroll
        for (int nt = 0; nt < 4; nt++) {
            int col = wid * 32 + nt * 8 + cpair;
            *(float2*)(g_O + ro0 + col) =
                make_float2(accd[mt][nt][0] * inv0, accd[mt][nt][1] * inv0);
            *(float2*)(g_O + ro1 + col) =
                make_float2(accd[mt][nt][2] * inv1, accd[mt][nt][3] * inv1);
        }
    }
    if (t < 64)
        g_den[s * LSEG + qt * 64 + t] = lsum2[t] + lsum2[64 + t];
}

// ================= Phase 3: combine (gather) ================================
__global__ __launch_bounds__(256) void combine_kernel(float* __restrict__ out)
{
    const int token = blockIdx.x * 4 + (threadIdx.x >> 6);
    const int lane  = threadIdx.x & 63;
    const int b = token >> 13, p = token & 8191;

    const int slot0 = (p >> 11) * 4 + b, j0 = p & 2047;
    float d0 = g_den[slot0 * LSEG + j0];
    float sum = d0;
    int slot1 = -1, j1 = 0, slot2 = -1, j2 = 0;
    float d1 = 0.f, d2 = 0.f;
    if ((p & 1) == 0) {
        slot1 = 16 + (p >> 12) * 4 + b; j1 = (p & 4095) >> 1;
        d1 = g_den[slot1 * LSEG + j1]; sum += d1;
    }
    if ((p & 3) == 0) {
        slot2 = 24 + b; j2 = p >> 2;
        d2 = g_den[slot2 * LSEG + j2]; sum += d2;
    }
    const float inv = 1.0f / sum;
    const int c = lane << 2;

    float4 o0 = *(const float4*)(g_O + ((long)slot0 * LSEG + j0) * DD + c);
    float a0 = d0 * inv;
    float4 res;
    res.x = o0.x * a0; res.y = o0.y * a0; res.z = o0.z * a0; res.w = o0.w * a0;
    if (slot1 >= 0) {
        float4 o1 = *(const float4*)(g_O + ((long)slot1 * LSEG + j1) * DD + c);
        float a1 = d1 * inv;
        res.x = fmaf(o1.x, a1, res.x); res.y = fmaf(o1.y, a1, res.y);
        res.z = fmaf(o1.z, a1, res.z); res.w = fmaf(o1.w, a1, res.w);
    }
    if (slot2 >= 0) {
        float4 o2v = *(const float4*)(g_O + ((long)slot2 * LSEG + j2) * DD + c);
        float a2 = d2 * inv;
        res.x = fmaf(o2v.x, a2, res.x); res.y = fmaf(o2v.y, a2, res.y);
        res.z = fmaf(o2v.z, a2, res.z); res.w = fmaf(o2v.w, a2, res.w);
    }
    *(float4*)(out + ((long)b * NN + p) * DD + c) = res;
}

// ================= launch ====================================================
extern "C" void kernel_launch(void* const* d_in, const int* in_sizes, int n_in,
                              void* d_out, int out_size)
{
    (void)in_sizes; (void)n_in; (void)out_size;
    const float* x  = (const float*)d_in[0];
    const float* Wq = (const float*)d_in[1];
    const float* Wk = (const float*)d_in[2];
    const float* Wv = (const float*)d_in[3];

    cudaFuncSetAttribute(qkv_mma_kernel, cudaFuncAttributeMaxDynamicSharedMemorySize,
                         QKV_SMEM);
    cudaFuncSetAttribute(attn_kernel, cudaFuncAttributeMaxDynamicSharedMemorySize,
                         SM_TOTAL);

    split_x_kernel<<<8192, 256>>>(x);
    split_w_kernel<<<dim3(8, 8, 3), 256>>>(Wq, Wk, Wv);
    qkv_mma_kernel<<<dim3(256, 2, 3), 256, QKV_SMEM>>>();
    transpose_v_kernel<<<dim3(64, 8, 28), 256>>>();
    attn_kernel<<<dim3(32, 28), 256, SM_TOTAL>>>();
    combine_kernel<<<8192, 256>>>((float*)d_out);
}

// round 12
// speedup vs baseline: 6.4502x; 1.0600x over previous
#include <cuda_runtime.h>
#include <cuda_bf16.h>
#include <cuda_fp16.h>
#include <stdint.h>
#include <math.h>

#define BB   4
#define NN   8192
#define CC   256
#define DD   256
#define LSEG 2048
#define NSEG 28

// ---------------- cp.async helpers -----------------------------------------
__device__ __forceinline__ uint32_t smem_to_u32(const void* p) {
    uint32_t a;
    asm("{ .reg .u64 t; cvta.to.shared.u64 t, %1; cvt.u32.u64 %0, t; }"
        : "=r"(a) : "l"(p));
    return a;
}
__device__ __forceinline__ void cp16(uint32_t dst, const void* src) {
    asm volatile("cp.async.cg.shared.global [%0], [%1], 16;" :: "r"(dst), "l"(src) : "memory");
}
#define CP_COMMIT() asm volatile("cp.async.commit_group;" ::: "memory")
#define CP_WAIT1()  asm volatile("cp.async.wait_group 1;" ::: "memory")
#define CP_WAIT0()  asm volatile("cp.async.wait_group 0;" ::: "memory")

// ---------------- ldmatrix / mma.sync ---------------------------------------
__device__ __forceinline__ void ldsm4(uint32_t (&d)[4], uint32_t addr) {
    asm volatile("ldmatrix.sync.aligned.m8n8.x4.shared.b16 {%0,%1,%2,%3}, [%4];"
        : "=r"(d[0]), "=r"(d[1]), "=r"(d[2]), "=r"(d[3]) : "r"(addr));
}
__device__ __forceinline__ void mma_fp16(float (&c)[4], const uint32_t (&a)[4],
                                         uint32_t b0, uint32_t b1) {
    asm volatile("mma.sync.aligned.m16n8k16.row.col.f32.f16.f16.f32 "
        "{%0,%1,%2,%3}, {%4,%5,%6,%7}, {%8,%9}, {%0,%1,%2,%3};"
        : "+f"(c[0]), "+f"(c[1]), "+f"(c[2]), "+f"(c[3])
        : "r"(a[0]), "r"(a[1]), "r"(a[2]), "r"(a[3]), "r"(b0), "r"(b1));
}

// A-fragment address (ldmatrix x4): 16 rows starting r0, k-step ks (16 elems)
__device__ __forceinline__ uint32_t aAddr(uint32_t base, int rowbytes, int r0,
                                          int ks, int lane) {
    int row = r0 + (lane & 7) + ((lane & 8) ? 8 : 0);
    int c16 = ks * 2 + (lane >> 4);
    return base + row * rowbytes + ((uint32_t)(c16 ^ (row & 7)) << 4);
}
// B-fragment address (ldmatrix x4): 8 rows at n0, TWO k-steps (pair kp)
__device__ __forceinline__ uint32_t b4Addr(uint32_t base, int rowbytes, int n0,
                                           int kp, int lane) {
    int row = n0 + (lane & 7);
    int c16 = kp * 4 + (lane >> 3);
    return base + row * rowbytes + ((uint32_t)(c16 ^ (row & 7)) << 4);
}
__device__ __forceinline__ uint32_t swz512(uint32_t base, int row, int c16) {
    return base + row * 512 + ((uint32_t)(c16 ^ (row & 7)) << 4);
}
__device__ __forceinline__ uint32_t swz128(uint32_t base, int row, int c16) {
    return base + row * 128 + ((uint32_t)(c16 ^ (row & 7)) << 4);
}

// ---------------- scratch ---------------------------------------------------
__device__ __half        g_Xf [BB * NN * CC];       // X single fp16
__device__ __half        g_Whf[3 * CC * DD];        // [z][n][k] transposed, fp16 hi
__device__ __half        g_Wlf[3 * CC * DD];        // fp16 lo
__device__ __half        g_Qf [BB * NN * DD];       // Q single fp16 (x 1/16)
__device__ __half        g_Kf [BB * NN * DD];       // K single fp16
__device__ float         g_V  [BB * NN * DD];
__device__ __half        g_Vtf[NSEG * DD * LSEG];   // per-slot V^T, single fp16
__device__ float g_O[NSEG * LSEG * DD];
__device__ float g_den[NSEG * LSEG];

__device__ __forceinline__ void slot_decode(int s, int& batch, int& posbase, int& r) {
    int w, base;
    if (s < 16)      { w = 2048; r = 1; base = 0;  }
    else if (s < 24) { w = 4096; r = 2; base = 16; }
    else             { w = 8192; r = 4; base = 24; }
    int local = s - base;
    batch = local & 3;
    posbase = (local >> 2) * w;
}

// ================= Phase 0a: convert X to single fp16 =======================
__global__ __launch_bounds__(256) void split_x_kernel(const float* __restrict__ X)
{
    long e = (long)blockIdx.x * 1024 + threadIdx.x * 4;
    float4 v = *(const float4*)(X + e);
    *(__half2*)(g_Xf + e)     = __floats2half2_rn(v.x, v.y);
    *(__half2*)(g_Xf + e + 2) = __floats2half2_rn(v.z, v.w);
}

// ================= Phase 0b: transpose+split W (fp16 hi/lo) =================
__global__ __launch_bounds__(256) void split_w_kernel(
    const float* __restrict__ Wq, const float* __restrict__ Wk,
    const float* __restrict__ Wv)
{
    __shared__ float T[32][33];
    const int z = blockIdx.z;
    const float* W = (z == 0) ? Wq : (z == 1) ? Wk : Wv;
    const int k0 = blockIdx.x * 32, n0 = blockIdx.y * 32;
    const int t = threadIdx.x;
    {
        int kk = t >> 3, n4 = (t & 7) << 2;
        float4 v = *(const float4*)(W + (long)(k0 + kk) * DD + n0 + n4);
        T[kk][n4] = v.x; T[kk][n4 + 1] = v.y; T[kk][n4 + 2] = v.z; T[kk][n4 + 3] = v.w;
    }
    __syncthreads();
    {
        int nn = t >> 3, k4 = (t & 7) << 2;
        float sc = (z == 0) ? 0.0625f : 1.0f;
        float v0 = T[k4][nn] * sc, v1 = T[k4 + 1][nn] * sc;
        float v2 = T[k4 + 2][nn] * sc, v3 = T[k4 + 3][nn] * sc;
        __half2 h0 = __floats2half2_rn(v0, v1);
        __half2 h1 = __floats2half2_rn(v2, v3);
        __half2 l0 = __floats2half2_rn(v0 - __half2float(h0.x),
                                       v1 - __half2float(h0.y));
        __half2 l1 = __floats2half2_rn(v2 - __half2float(h1.x),
                                       v3 - __half2float(h1.y));
        long off = (long)z * (CC * DD) + (long)(n0 + nn) * CC + k0 + k4;
        *(__half2*)(g_Whf + off) = h0; *(__half2*)(g_Whf + off + 2) = h1;
        *(__half2*)(g_Wlf + off) = l0; *(__half2*)(g_Wlf + off + 2) = l1;
    }
}

// ================= Phase 1: QKV projection via mma.sync =====================
// X single fp16 x W (fp16 hi+lo): 2 terms (W split exact).
#define GX   0
#define GW_H 32768
#define GW_L 65536
#define QKV_SMEM 98304

__global__ __launch_bounds__(256, 2) void qkv_mma_kernel()
{
    extern __shared__ char smem[];
    const uint32_t sb = smem_to_u32(smem);
    const int t = threadIdx.x, lane = t & 31, wid = t >> 5;
    const int m0 = blockIdx.x * 128, n0 = blockIdx.y * 128, z = blockIdx.z;
    const __half* Wh = g_Whf + (long)z * (CC * DD);
    const __half* Wl = g_Wlf + (long)z * (CC * DD);

    auto loadslab = [&](int s, int buf) {
        int k0 = s * 64;
        uint32_t bo = (uint32_t)buf * 16384;
#pragma unroll
        for (int i = 0; i < 4; i++) {
            int e = t + i * 256;
            int row = e >> 3, c16 = e & 7;
            long xs = (long)(m0 + row) * CC + k0 + c16 * 8;
            cp16(swz128(sb + GX + bo, row, c16), (const void*)(g_Xf + xs));
            long ws = (long)(n0 + row) * CC + k0 + c16 * 8;
            cp16(swz128(sb + GW_H + bo, row, c16), (const void*)(Wh + ws));
            cp16(swz128(sb + GW_L + bo, row, c16), (const void*)(Wl + ws));
        }
    };

    float acc[16][4];
#pragma unroll
    for (int nt = 0; nt < 16; nt++)
#pragma unroll
        for (int c = 0; c < 4; c++) acc[nt][c] = 0.f;

    loadslab(0, 0); CP_COMMIT();
    for (int s = 0; s < 4; s++) {
        if (s < 3) { loadslab(s + 1, (s + 1) & 1); CP_COMMIT(); CP_WAIT1(); }
        else CP_WAIT0();
        __syncthreads();
        uint32_t bo = (uint32_t)(s & 1) * 16384;
#pragma unroll
        for (int kp = 0; kp < 2; kp++) {
            uint32_t af0[4], af1[4];
            ldsm4(af0, aAddr(sb + GX + bo, 128, wid * 16, 2 * kp,     lane));
            ldsm4(af1, aAddr(sb + GX + bo, 128, wid * 16, 2 * kp + 1, lane));
#pragma unroll
            for (int nt = 0; nt < 16; nt++) {
                uint32_t bh[4], bl[4];
                ldsm4(bh, b4Addr(sb + GW_H + bo, 128, nt * 8, kp, lane));
                ldsm4(bl, b4Addr(sb + GW_L + bo, 128, nt * 8, kp, lane));
                mma_fp16(acc[nt], af0, bh[0], bh[1]);
                mma_fp16(acc[nt], af0, bl[0], bl[1]);
                mma_fp16(acc[nt], af1, bh[2], bh[3]);
                mma_fp16(acc[nt], af1, bl[2], bl[3]);
            }
        }
        __syncthreads();
    }

    const int g = lane >> 2, cpair = 2 * (lane & 3);
#pragma unroll
    for (int nt = 0; nt < 16; nt++) {
        long r0 = (long)(m0 + wid * 16 + g) * DD + n0 + nt * 8 + cpair;
        long r1 = r0 + 8 * DD;
        if (z == 2) {
            *(float2*)(g_V + r0) = make_float2(acc[nt][0], acc[nt][1]);
            *(float2*)(g_V + r1) = make_float2(acc[nt][2], acc[nt][3]);
        } else {
            __half* dst = (z == 0) ? g_Qf : g_Kf;
            *(__half2*)(dst + r0) = __floats2half2_rn(acc[nt][0], acc[nt][1]);
            *(__half2*)(dst + r1) = __floats2half2_rn(acc[nt][2], acc[nt][3]);
        }
    }
}

// ================= Phase 1b: per-slot V^T gather (single fp16) ==============
__global__ __launch_bounds__(256) void transpose_v_kernel()
{
    __shared__ float T[32][36];
    const int s = blockIdx.z, jt = blockIdx.x, dt = blockIdx.y;
    int batch, posbase, r;
    slot_decode(s, batch, posbase, r);

    const int t = threadIdx.x;
    {
        int jl = t >> 3, dq = (t & 7) << 2;
        int pos = posbase + (jt * 32 + jl) * r;
        float4 v = *(const float4*)(g_V + ((long)batch * NN + pos) * DD + dt * 32 + dq);
        T[jl][dq] = v.x; T[jl][dq + 1] = v.y; T[jl][dq + 2] = v.z; T[jl][dq + 3] = v.w;
    }
    __syncthreads();
    {
        int dl = t >> 3, jq = (t & 7) << 2;
        __half2 h0 = __floats2half2_rn(T[jq][dl], T[jq + 1][dl]);
        __half2 h1 = __floats2half2_rn(T[jq + 2][dl], T[jq + 3][dl]);
        long off = ((long)s * DD + dt * 32 + dl) * LSEG + jt * 32 + jq;
        *(__half2*)(g_Vtf + off) = h0;
        *(__half2*)(g_Vtf + off + 2) = h1;
    }
}

// ================= Phase 2: mma.sync fp16 causal attention ==================
// S: Qf x Kf, single fp16 term.  PV: P(fp16) x V(fp16), single term.
// 2 CTAs/SM (104.5KB smem each) for cross-CTA phase overlap.
#define OQ  0
#define OK  32768
#define OV  65536
#define OP  98304
#define OLS 106496
#define SM_TOTAL (OLS + 512)

__global__ __launch_bounds__(256, 2) void attn_kernel()
{
    extern __shared__ char smem[];
    const uint32_t sb = smem_to_u32(smem);
    float* lsum2 = (float*)(smem + OLS);

    const int t = threadIdx.x, lane = t & 31, wid = t >> 5;
    const int qt = 31 - (int)blockIdx.x;          // heavy tiles first
    const int s  = blockIdx.y;
    int batch, posbase, r;
    slot_decode(s, batch, posbase, r);
    const long qkvoff = (long)batch * (NN * DD);

    auto issueK = [&](int kt) {
#pragma unroll
        for (int i = 0; i < 8; i++) {
            int e = t + i * 256;
            int key = e >> 5, c16 = e & 31;
            cp16(swz512(sb + OK, key, c16),
                 (const void*)(g_Kf + qkvoff +
                 ((long)(posbase + (kt * 64 + key) * r)) * DD + c16 * 8));
        }
    };
    auto issueV = [&](int kt) {
#pragma unroll
        for (int i = 0; i < 8; i++) {
            int e = t + i * 256;
            int d = e >> 3, c16 = e & 7;
            cp16(swz128(sb + OV, d, c16),
                 (const void*)(g_Vtf + (long)s * DD * LSEG +
                               (long)d * LSEG + kt * 64 + c16 * 8));
        }
    };

    // prologue: Q tile + K(0)
    {
#pragma unroll
        for (int i = 0; i < 8; i++) {
            int e = t + i * 256;
            int row = e >> 5, c16 = e & 31;
            cp16(swz512(sb + OQ, row, c16),
                 (const void*)(g_Qf + qkvoff +
                 ((long)(posbase + (qt * 64 + row) * r)) * DD + c16 * 8));
        }
        CP_COMMIT();
        issueK(0); CP_COMMIT();
    }

    const int g = lane >> 2, cpair = 2 * (lane & 3);
    const int wq = wid & 3, wk = wid >> 2;
    float accd[4][4][4];
#pragma unroll
    for (int mt = 0; mt < 4; mt++)
#pragma unroll
        for (int nt = 0; nt < 4; nt++)
#pragma unroll
            for (int c = 0; c < 4; c++) accd[mt][nt][c] = 0.f;
    float rs0 = 0.f, rs1 = 0.f;

    for (int kt = 0; kt <= qt; kt++) {
        __syncthreads();                          // V buf free (prev PV done)
        issueV(kt); CP_COMMIT();
        CP_WAIT1();                               // Q + K(kt) landed
        __syncthreads();

        // ---- S = Q K^T: warp does 16q x 32k, single fp16 term -------------
        float sacc[4][4];
#pragma unroll
        for (int nt = 0; nt < 4; nt++)
#pragma unroll
            for (int c = 0; c < 4; c++) sacc[nt][c] = 0.f;
#pragma unroll 4
        for (int kp = 0; kp < 8; kp++) {
            uint32_t ah0[4], ah1[4];
            ldsm4(ah0, aAddr(sb + OQ, 512, wq * 16, 2 * kp,     lane));
            ldsm4(ah1, aAddr(sb + OQ, 512, wq * 16, 2 * kp + 1, lane));
#pragma unroll
            for (int nt = 0; nt < 4; nt++) {
                uint32_t bh[4];
                ldsm4(bh, b4Addr(sb + OK, 512, wk * 32 + nt * 8, kp, lane));
                mma_fp16(sacc[nt], ah0, bh[0], bh[1]);
                mma_fp16(sacc[nt], ah1, bh[2], bh[3]);
            }
        }

        // ---- softmax: mask, exp, row-sum, pack P (single fp16) -------------
        const int prow0 = wq * 16 + g, prow1 = prow0 + 8;
        const int qrow0 = qt * 64 + prow0, qrow1 = qt * 64 + prow1;
#pragma unroll
        for (int nt = 0; nt < 4; nt++) {
            int kcol = wk * 32 + nt * 8 + cpair;
            int kg = kt * 64 + kcol;
            float p00 = (kg     <= qrow0) ? __expf(sacc[nt][0]) : 0.f;
            float p01 = (kg + 1 <= qrow0) ? __expf(sacc[nt][1]) : 0.f;
            float p10 = (kg     <= qrow1) ? __expf(sacc[nt][2]) : 0.f;
            float p11 = (kg + 1 <= qrow1) ? __expf(sacc[nt][3]) : 0.f;
            rs0 += p00 + p01;
            rs1 += p10 + p11;
            __half2 h0 = __floats2half2_rn(p00, p01);
            __half2 h1 = __floats2half2_rn(p10, p11);
            uint32_t ob0 = prow0 * 128 + ((uint32_t)((kcol >> 3) ^ (prow0 & 7)) << 4)
                         + (kcol & 7) * 2;
            uint32_t ob1 = prow1 * 128 + ((uint32_t)((kcol >> 3) ^ (prow1 & 7)) << 4)
                         + (kcol & 7) * 2;
            *(__half2*)(smem + OP + ob0) = h0;
            *(__half2*)(smem + OP + ob1) = h1;
        }
        __syncthreads();                          // P visible; K buf free

        // ---- prefetch next K (overlaps PV), then wait V --------------------
        if (kt < qt) { issueK(kt + 1); CP_COMMIT(); CP_WAIT1(); }
        else CP_WAIT0();
        __syncthreads();                          // V visible to all

        // ---- D += P V: warp owns 32 d-cols; single fp16 term ---------------
        const int n0 = wid * 32;
#pragma unroll
        for (int kp = 0; kp < 2; kp++) {
            uint32_t bh[4][4];
#pragma unroll
            for (int nt = 0; nt < 4; nt++)
                ldsm4(bh[nt], b4Addr(sb + OV, 128, n0 + nt * 8, kp, lane));
#pragma unroll
            for (int mt = 0; mt < 4; mt++) {
                uint32_t ah0[4], ah1[4];
                ldsm4(ah0, aAddr(sb + OP, 128, mt * 16, 2 * kp,     lane));
                ldsm4(ah1, aAddr(sb + OP, 128, mt * 16, 2 * kp + 1, lane));
#pragma unroll
                for (int nt = 0; nt < 4; nt++) {
                    mma_fp16(accd[mt][nt], ah0, bh[nt][0], bh[nt][1]);
                    mma_fp16(accd[mt][nt], ah1, bh[nt][2], bh[nt][3]);
                }
            }
        }
    }

    // ---- epilogue ---------------------------------------------------------
    rs0 += __shfl_xor_sync(0xffffffffu, rs0, 1);
    rs0 += __shfl_xor_sync(0xffffffffu, rs0, 2);
    rs1 += __shfl_xor_sync(0xffffffffu, rs1, 1);
    rs1 += __shfl_xor_sync(0xffffffffu, rs1, 2);
    if ((lane & 3) == 0) {
        lsum2[wk * 64 + wq * 16 + g]     = rs0;
        lsum2[wk * 64 + wq * 16 + g + 8] = rs1;
    }
    __syncthreads();

#pragma unroll
    for (int mt = 0; mt < 4; mt++) {
        int lr0 = mt * 16 + g, lr1 = lr0 + 8;
        float inv0 = 1.0f / (lsum2[lr0] + lsum2[64 + lr0]);
        float inv1 = 1.0f / (lsum2[lr1] + lsum2[64 + lr1]);
        long ro0 = (long)(s * LSEG + qt * 64 + lr0) * DD;
        long ro1 = (long)(s * LSEG + qt * 64 + lr1) * DD;
#pragma unroll
        for (int nt = 0; nt < 4; nt++) {
            int col = wid * 32 + nt * 8 + cpair;
            *(float2*)(g_O + ro0 + col) =
                make_float2(accd[mt][nt][0] * inv0, accd[mt][nt][1] * inv0);
            *(float2*)(g_O + ro1 + col) =
                make_float2(accd[mt][nt][2] * inv1, accd[mt][nt][3] * inv1);
        }
    }
    if (t < 64)
        g_den[s * LSEG + qt * 64 + t] = lsum2[t] + lsum2[64 + t];
}

// ================= Phase 3: combine (gather) ================================
__global__ __launch_bounds__(256) void combine_kernel(float* __restrict__ out)
{
    const int token = blockIdx.x * 4 + (threadIdx.x >> 6);
    const int lane  = threadIdx.x & 63;
    const int b = token >> 13, p = token & 8191;

    const int slot0 = (p >> 11) * 4 + b, j0 = p & 2047;
    float d0 = g_den[slot0 * LSEG + j0];
    float sum = d0;
    int slot1 = -1, j1 = 0, slot2 = -1, j2 = 0;
    float d1 = 0.f, d2 = 0.f;
    if ((p & 1) == 0) {
        slot1 = 16 + (p >> 12) * 4 + b; j1 = (p & 4095) >> 1;
        d1 = g_den[slot1 * LSEG + j1]; sum += d1;
    }
    if ((p & 3) == 0) {
        slot2 = 24 + b; j2 = p >> 2;
        d2 = g_den[slot2 * LSEG + j2]; sum += d2;
    }
    const float inv = 1.0f / sum;
    const int c = lane << 2;

    float4 o0 = *(const float4*)(g_O + ((long)slot0 * LSEG + j0) * DD + c);
    float a0 = d0 * inv;
    float4 res;
    res.x = o0.x * a0; res.y = o0.y * a0; res.z = o0.z * a0; res.w = o0.w * a0;
    if (slot1 >= 0) {
        float4 o1 = *(const float4*)(g_O + ((long)slot1 * LSEG + j1) * DD + c);
        float a1 = d1 * inv;
        res.x = fmaf(o1.x, a1, res.x); res.y = fmaf(o1.y, a1, res.y);
        res.z = fmaf(o1.z, a1, res.z); res.w = fmaf(o1.w, a1, res.w);
    }
    if (slot2 >= 0) {
        float4 o2v = *(const float4*)(g_O + ((long)slot2 * LSEG + j2) * DD + c);
        float a2 = d2 * inv;
        res.x = fmaf(o2v.x, a2, res.x); res.y = fmaf(o2v.y, a2, res.y);
        res.z = fmaf(o2v.z, a2, res.z); res.w = fmaf(o2v.w, a2, res.w);
    }
    *(float4*)(out + ((long)b * NN + p) * DD + c) = res;
}

// ================= launch ====================================================
extern "C" void kernel_launch(void* const* d_in, const int* in_sizes, int n_in,
                              void* d_out, int out_size)
{
    (void)in_sizes; (void)n_in; (void)out_size;
    const float* x  = (const float*)d_in[0];
    const float* Wq = (const float*)d_in[1];
    const float* Wk = (const float*)d_in[2];
    const float* Wv = (const float*)d_in[3];

    cudaFuncSetAttribute(qkv_mma_kernel, cudaFuncAttributeMaxDynamicSharedMemorySize,
                         QKV_SMEM);
    cudaFuncSetAttribute(attn_kernel, cudaFuncAttributeMaxDynamicSharedMemorySize,
                         SM_TOTAL);

    split_x_kernel<<<8192, 256>>>(x);
    split_w_kernel<<<dim3(8, 8, 3), 256>>>(Wq, Wk, Wv);
    qkv_mma_kernel<<<dim3(256, 2, 3), 256, QKV_SMEM>>>();
    transpose_v_kernel<<<dim3(64, 8, 28), 256>>>();
    attn_kernel<<<dim3(32, 28), 256, SM_TOTAL>>>();
    combine_kernel<<<8192, 256>>>((float*)d_out);
}

// round 13
// speedup vs baseline: 6.8505x; 1.0620x over previous
#include <cuda_runtime.h>
#include <cuda_bf16.h>
#include <cuda_fp16.h>
#include <stdint.h>
#include <math.h>

#define BB   4
#define NN   8192
#define CC   256
#define DD   256
#define LSEG 2048
#define NSEG 28

// ---------------- cp.async helpers -----------------------------------------
__device__ __forceinline__ uint32_t smem_to_u32(const void* p) {
    uint32_t a;
    asm("{ .reg .u64 t; cvta.to.shared.u64 t, %1; cvt.u32.u64 %0, t; }"
        : "=r"(a) : "l"(p));
    return a;
}
__device__ __forceinline__ void cp16(uint32_t dst, const void* src) {
    asm volatile("cp.async.cg.shared.global [%0], [%1], 16;" :: "r"(dst), "l"(src) : "memory");
}
#define CP_COMMIT() asm volatile("cp.async.commit_group;" ::: "memory")
#define CP_WAIT1()  asm volatile("cp.async.wait_group 1;" ::: "memory")
#define CP_WAIT0()  asm volatile("cp.async.wait_group 0;" ::: "memory")

// ---------------- ldmatrix / mma.sync ---------------------------------------
__device__ __forceinline__ void ldsm4(uint32_t (&d)[4], uint32_t addr) {
    asm volatile("ldmatrix.sync.aligned.m8n8.x4.shared.b16 {%0,%1,%2,%3}, [%4];"
        : "=r"(d[0]), "=r"(d[1]), "=r"(d[2]), "=r"(d[3]) : "r"(addr));
}
__device__ __forceinline__ void ldsm4t(uint32_t (&d)[4], uint32_t addr) {
    asm volatile("ldmatrix.sync.aligned.m8n8.x4.trans.shared.b16 {%0,%1,%2,%3}, [%4];"
        : "=r"(d[0]), "=r"(d[1]), "=r"(d[2]), "=r"(d[3]) : "r"(addr));
}
__device__ __forceinline__ void mma_fp16(float (&c)[4], const uint32_t (&a)[4],
                                         uint32_t b0, uint32_t b1) {
    asm volatile("mma.sync.aligned.m16n8k16.row.col.f32.f16.f16.f32 "
        "{%0,%1,%2,%3}, {%4,%5,%6,%7}, {%8,%9}, {%0,%1,%2,%3};"
        : "+f"(c[0]), "+f"(c[1]), "+f"(c[2]), "+f"(c[3])
        : "r"(a[0]), "r"(a[1]), "r"(a[2]), "r"(a[3]), "r"(b0), "r"(b1));
}

// A-fragment address (ldmatrix x4): 16 rows starting r0, k-step ks (16 elems)
__device__ __forceinline__ uint32_t aAddr(uint32_t base, int rowbytes, int r0,
                                          int ks, int lane) {
    int row = r0 + (lane & 7) + ((lane & 8) ? 8 : 0);
    int c16 = ks * 2 + (lane >> 4);
    return base + row * rowbytes + ((uint32_t)(c16 ^ (row & 7)) << 4);
}
// B-fragment address (ldmatrix x4): 8 rows at n0, TWO k-steps (pair kp)
__device__ __forceinline__ uint32_t b4Addr(uint32_t base, int rowbytes, int n0,
                                           int kp, int lane) {
    int row = n0 + (lane & 7);
    int c16 = kp * 4 + (lane >> 3);
    return base + row * rowbytes + ((uint32_t)(c16 ^ (row & 7)) << 4);
}
// trans B-fragment address (ldmatrix x4 .trans): 16 key-rows at k0, two n8
// tiles at 16B-chunks c16base, c16base+1 of a key-major matrix.
__device__ __forceinline__ uint32_t bTAddr(uint32_t base, int rowbytes, int k0,
                                           int c16base, int lane) {
    int row = k0 + (lane & 7) + ((lane & 8) ? 8 : 0);
    int c16 = c16base + (lane >> 4);
    return base + row * rowbytes + ((uint32_t)(c16 ^ (row & 7)) << 4);
}
__device__ __forceinline__ uint32_t swz512(uint32_t base, int row, int c16) {
    return base + row * 512 + ((uint32_t)(c16 ^ (row & 7)) << 4);
}
__device__ __forceinline__ uint32_t swz128(uint32_t base, int row, int c16) {
    return base + row * 128 + ((uint32_t)(c16 ^ (row & 7)) << 4);
}

// ---------------- scratch ---------------------------------------------------
__device__ __half        g_Xf [BB * NN * CC];       // X single fp16
__device__ __half        g_Whf[3 * CC * DD];        // [z][n][k] transposed, fp16 hi
__device__ __half        g_Wlf[3 * CC * DD];        // fp16 lo
__device__ __half        g_Qf [BB * NN * DD];       // Q single fp16 (x 1/16)
__device__ __half        g_Kf [BB * NN * DD];       // K single fp16
__device__ __half        g_Vf [BB * NN * DD];       // V single fp16 (token-major)
__device__ float g_O[NSEG * LSEG * DD];
__device__ float g_den[NSEG * LSEG];

__device__ __forceinline__ void slot_decode(int s, int& batch, int& posbase, int& r) {
    int w, base;
    if (s < 16)      { w = 2048; r = 1; base = 0;  }
    else if (s < 24) { w = 4096; r = 2; base = 16; }
    else             { w = 8192; r = 4; base = 24; }
    int local = s - base;
    batch = local & 3;
    posbase = (local >> 2) * w;
}

// ================= Phase 0a: convert X to single fp16 =======================
__global__ __launch_bounds__(256) void split_x_kernel(const float* __restrict__ X)
{
    long e = (long)blockIdx.x * 1024 + threadIdx.x * 4;
    float4 v = *(const float4*)(X + e);
    *(__half2*)(g_Xf + e)     = __floats2half2_rn(v.x, v.y);
    *(__half2*)(g_Xf + e + 2) = __floats2half2_rn(v.z, v.w);
}

// ================= Phase 0b: transpose+split W (fp16 hi/lo) =================
__global__ __launch_bounds__(256) void split_w_kernel(
    const float* __restrict__ Wq, const float* __restrict__ Wk,
    const float* __restrict__ Wv)
{
    __shared__ float T[32][33];
    const int z = blockIdx.z;
    const float* W = (z == 0) ? Wq : (z == 1) ? Wk : Wv;
    const int k0 = blockIdx.x * 32, n0 = blockIdx.y * 32;
    const int t = threadIdx.x;
    {
        int kk = t >> 3, n4 = (t & 7) << 2;
        float4 v = *(const float4*)(W + (long)(k0 + kk) * DD + n0 + n4);
        T[kk][n4] = v.x; T[kk][n4 + 1] = v.y; T[kk][n4 + 2] = v.z; T[kk][n4 + 3] = v.w;
    }
    __syncthreads();
    {
        int nn = t >> 3, k4 = (t & 7) << 2;
        float sc = (z == 0) ? 0.0625f : 1.0f;
        float v0 = T[k4][nn] * sc, v1 = T[k4 + 1][nn] * sc;
        float v2 = T[k4 + 2][nn] * sc, v3 = T[k4 + 3][nn] * sc;
        __half2 h0 = __floats2half2_rn(v0, v1);
        __half2 h1 = __floats2half2_rn(v2, v3);
        __half2 l0 = __floats2half2_rn(v0 - __half2float(h0.x),
                                       v1 - __half2float(h0.y));
        __half2 l1 = __floats2half2_rn(v2 - __half2float(h1.x),
                                       v3 - __half2float(h1.y));
        long off = (long)z * (CC * DD) + (long)(n0 + nn) * CC + k0 + k4;
        *(__half2*)(g_Whf + off) = h0; *(__half2*)(g_Whf + off + 2) = h1;
        *(__half2*)(g_Wlf + off) = l0; *(__half2*)(g_Wlf + off + 2) = l1;
    }
}

// ================= Phase 1: QKV projection via mma.sync =====================
// X single fp16 x W (fp16 hi+lo): 2 terms (W split exact).
#define GX   0
#define GW_H 32768
#define GW_L 65536
#define QKV_SMEM 98304

__global__ __launch_bounds__(256, 2) void qkv_mma_kernel()
{
    extern __shared__ char smem[];
    const uint32_t sb = smem_to_u32(smem);
    const int t = threadIdx.x, lane = t & 31, wid = t >> 5;
    const int m0 = blockIdx.x * 128, n0 = blockIdx.y * 128, z = blockIdx.z;
    const __half* Wh = g_Whf + (long)z * (CC * DD);
    const __half* Wl = g_Wlf + (long)z * (CC * DD);

    auto loadslab = [&](int s, int buf) {
        int k0 = s * 64;
        uint32_t bo = (uint32_t)buf * 16384;
#pragma unroll
        for (int i = 0; i < 4; i++) {
            int e = t + i * 256;
            int row = e >> 3, c16 = e & 7;
            long xs = (long)(m0 + row) * CC + k0 + c16 * 8;
            cp16(swz128(sb + GX + bo, row, c16), (const void*)(g_Xf + xs));
            long ws = (long)(n0 + row) * CC + k0 + c16 * 8;
            cp16(swz128(sb + GW_H + bo, row, c16), (const void*)(Wh + ws));
            cp16(swz128(sb + GW_L + bo, row, c16), (const void*)(Wl + ws));
        }
    };

    float acc[16][4];
#pragma unroll
    for (int nt = 0; nt < 16; nt++)
#pragma unroll
        for (int c = 0; c < 4; c++) acc[nt][c] = 0.f;

    loadslab(0, 0); CP_COMMIT();
    for (int s = 0; s < 4; s++) {
        if (s < 3) { loadslab(s + 1, (s + 1) & 1); CP_COMMIT(); CP_WAIT1(); }
        else CP_WAIT0();
        __syncthreads();
        uint32_t bo = (uint32_t)(s & 1) * 16384;
#pragma unroll
        for (int kp = 0; kp < 2; kp++) {
            uint32_t af0[4], af1[4];
            ldsm4(af0, aAddr(sb + GX + bo, 128, wid * 16, 2 * kp,     lane));
            ldsm4(af1, aAddr(sb + GX + bo, 128, wid * 16, 2 * kp + 1, lane));
#pragma unroll
            for (int nt = 0; nt < 16; nt++) {
                uint32_t bh[4], bl[4];
                ldsm4(bh, b4Addr(sb + GW_H + bo, 128, nt * 8, kp, lane));
                ldsm4(bl, b4Addr(sb + GW_L + bo, 128, nt * 8, kp, lane));
                mma_fp16(acc[nt], af0, bh[0], bh[1]);
                mma_fp16(acc[nt], af0, bl[0], bl[1]);
                mma_fp16(acc[nt], af1, bh[2], bh[3]);
                mma_fp16(acc[nt], af1, bl[2], bl[3]);
            }
        }
        __syncthreads();
    }

    const int g = lane >> 2, cpair = 2 * (lane & 3);
    __half* dst = (z == 0) ? g_Qf : (z == 1) ? g_Kf : g_Vf;
#pragma unroll
    for (int nt = 0; nt < 16; nt++) {
        long r0 = (long)(m0 + wid * 16 + g) * DD + n0 + nt * 8 + cpair;
        long r1 = r0 + 8 * DD;
        *(__half2*)(dst + r0) = __floats2half2_rn(acc[nt][0], acc[nt][1]);
        *(__half2*)(dst + r1) = __floats2half2_rn(acc[nt][2], acc[nt][3]);
    }
}

// ================= Phase 2: mma.sync fp16 causal attention ==================
// S: Qf x Kf.  PV: P(fp16) x V(fp16), V loaded key-major, B-frags via
// ldmatrix.trans (no V^T pre-pass).  2 CTAs/SM.
#define OQ  0
#define OK  32768
#define OV  65536
#define OP  98304
#define OLS 106496
#define SM_TOTAL (OLS + 512)

__global__ __launch_bounds__(256, 2) void attn_kernel()
{
    extern __shared__ char smem[];
    const uint32_t sb = smem_to_u32(smem);
    float* lsum2 = (float*)(smem + OLS);

    const int t = threadIdx.x, lane = t & 31, wid = t >> 5;
    const int qt = 31 - (int)blockIdx.x;          // heavy tiles first
    const int s  = blockIdx.y;
    int batch, posbase, r;
    slot_decode(s, batch, posbase, r);
    const long qkvoff = (long)batch * (NN * DD);

    auto issueK = [&](int kt) {
#pragma unroll
        for (int i = 0; i < 8; i++) {
            int e = t + i * 256;
            int key = e >> 5, c16 = e & 31;
            cp16(swz512(sb + OK, key, c16),
                 (const void*)(g_Kf + qkvoff +
                 ((long)(posbase + (kt * 64 + key) * r)) * DD + c16 * 8));
        }
    };
    auto issueV = [&](int kt) {
#pragma unroll
        for (int i = 0; i < 8; i++) {
            int e = t + i * 256;
            int key = e >> 5, c16 = e & 31;
            cp16(swz512(sb + OV, key, c16),
                 (const void*)(g_Vf + qkvoff +
                 ((long)(posbase + (kt * 64 + key) * r)) * DD + c16 * 8));
        }
    };

    // prologue: Q tile + K(0)
    {
#pragma unroll
        for (int i = 0; i < 8; i++) {
            int e = t + i * 256;
            int row = e >> 5, c16 = e & 31;
            cp16(swz512(sb + OQ, row, c16),
                 (const void*)(g_Qf + qkvoff +
                 ((long)(posbase + (qt * 64 + row) * r)) * DD + c16 * 8));
        }
        CP_COMMIT();
        issueK(0); CP_COMMIT();
    }

    const int g = lane >> 2, cpair = 2 * (lane & 3);
    const int wq = wid & 3, wk = wid >> 2;
    float accd[4][4][4];
#pragma unroll
    for (int mt = 0; mt < 4; mt++)
#pragma unroll
        for (int nt = 0; nt < 4; nt++)
#pragma unroll
            for (int c = 0; c < 4; c++) accd[mt][nt][c] = 0.f;
    float rs0 = 0.f, rs1 = 0.f;

    for (int kt = 0; kt <= qt; kt++) {
        __syncthreads();                          // V buf free (prev PV done)
        issueV(kt); CP_COMMIT();
        CP_WAIT1();                               // Q + K(kt) landed
        __syncthreads();

        // ---- S = Q K^T: warp does 16q x 32k, single fp16 term -------------
        float sacc[4][4];
#pragma unroll
        for (int nt = 0; nt < 4; nt++)
#pragma unroll
            for (int c = 0; c < 4; c++) sacc[nt][c] = 0.f;
#pragma unroll 4
        for (int kp = 0; kp < 8; kp++) {
            uint32_t ah0[4], ah1[4];
            ldsm4(ah0, aAddr(sb + OQ, 512, wq * 16, 2 * kp,     lane));
            ldsm4(ah1, aAddr(sb + OQ, 512, wq * 16, 2 * kp + 1, lane));
#pragma unroll
            for (int nt = 0; nt < 4; nt++) {
                uint32_t bh[4];
                ldsm4(bh, b4Addr(sb + OK, 512, wk * 32 + nt * 8, kp, lane));
                mma_fp16(sacc[nt], ah0, bh[0], bh[1]);
                mma_fp16(sacc[nt], ah1, bh[2], bh[3]);
            }
        }

        // ---- softmax: mask, exp, row-sum, pack P (single fp16) -------------
        const int prow0 = wq * 16 + g, prow1 = prow0 + 8;
        const int qrow0 = qt * 64 + prow0, qrow1 = qt * 64 + prow1;
#pragma unroll
        for (int nt = 0; nt < 4; nt++) {
            int kcol = wk * 32 + nt * 8 + cpair;
            int kg = kt * 64 + kcol;
            float p00 = (kg     <= qrow0) ? __expf(sacc[nt][0]) : 0.f;
            float p01 = (kg + 1 <= qrow0) ? __expf(sacc[nt][1]) : 0.f;
            float p10 = (kg     <= qrow1) ? __expf(sacc[nt][2]) : 0.f;
            float p11 = (kg + 1 <= qrow1) ? __expf(sacc[nt][3]) : 0.f;
            rs0 += p00 + p01;
            rs1 += p10 + p11;
            __half2 h0 = __floats2half2_rn(p00, p01);
            __half2 h1 = __floats2half2_rn(p10, p11);
            uint32_t ob0 = prow0 * 128 + ((uint32_t)((kcol >> 3) ^ (prow0 & 7)) << 4)
                         + (kcol & 7) * 2;
            uint32_t ob1 = prow1 * 128 + ((uint32_t)((kcol >> 3) ^ (prow1 & 7)) << 4)
                         + (kcol & 7) * 2;
            *(__half2*)(smem + OP + ob0) = h0;
            *(__half2*)(smem + OP + ob1) = h1;
        }
        __syncthreads();                          // P visible; K buf free

        // ---- prefetch next K (overlaps PV), then wait V --------------------
        if (kt < qt) { issueK(kt + 1); CP_COMMIT(); CP_WAIT1(); }
        else CP_WAIT0();
        __syncthreads();                          // V visible to all

        // ---- D += P V: warp owns 32 d-cols; B-frags from key-major V via
        //      ldmatrix.trans (one ldsm4t = k16 x two n8 tiles) ---------------
        const int n0 = wid * 32;
        const int c16b = n0 >> 3;
#pragma unroll
        for (int kp = 0; kp < 4; kp++) {          // 16 keys per step
            uint32_t bt0[4], bt1[4];
            ldsm4t(bt0, bTAddr(sb + OV, 512, kp * 16, c16b,     lane));
            ldsm4t(bt1, bTAddr(sb + OV, 512, kp * 16, c16b + 2, lane));
#pragma unroll
            for (int mt = 0; mt < 4; mt++) {
                uint32_t ah[4];
                ldsm4(ah, aAddr(sb + OP, 128, mt * 16, kp, lane));
                mma_fp16(accd[mt][0], ah, bt0[0], bt0[1]);
                mma_fp16(accd[mt][1], ah, bt0[2], bt0[3]);
                mma_fp16(accd[mt][2], ah, bt1[0], bt1[1]);
                mma_fp16(accd[mt][3], ah, bt1[2], bt1[3]);
            }
        }
    }

    // ---- epilogue ---------------------------------------------------------
    rs0 += __shfl_xor_sync(0xffffffffu, rs0, 1);
    rs0 += __shfl_xor_sync(0xffffffffu, rs0, 2);
    rs1 += __shfl_xor_sync(0xffffffffu, rs1, 1);
    rs1 += __shfl_xor_sync(0xffffffffu, rs1, 2);
    if ((lane & 3) == 0) {
        lsum2[wk * 64 + wq * 16 + g]     = rs0;
        lsum2[wk * 64 + wq * 16 + g + 8] = rs1;
    }
    __syncthreads();

#pragma unroll
    for (int mt = 0; mt < 4; mt++) {
        int lr0 = mt * 16 + g, lr1 = lr0 + 8;
        float inv0 = 1.0f / (lsum2[lr0] + lsum2[64 + lr0]);
        float inv1 = 1.0f / (lsum2[lr1] + lsum2[64 + lr1]);
        long ro0 = (long)(s * LSEG + qt * 64 + lr0) * DD;
        long ro1 = (long)(s * LSEG + qt * 64 + lr1) * DD;
#pragma unroll
        for (int nt = 0; nt < 4; nt++) {
            int col = wid * 32 + nt * 8 + cpair;
            *(float2*)(g_O + ro0 + col) =
                make_float2(accd[mt][nt][0] * inv0, accd[mt][nt][1] * inv0);
            *(float2*)(g_O + ro1 + col) =
                make_float2(accd[mt][nt][2] * inv1, accd[mt][nt][3] * inv1);
        }
    }
    if (t < 64)
        g_den[s * LSEG + qt * 64 + t] = lsum2[t] + lsum2[64 + t];
}

// ================= Phase 3: combine (gather) ================================
__global__ __launch_bounds__(256) void combine_kernel(float* __restrict__ out)
{
    const int token = blockIdx.x * 4 + (threadIdx.x >> 6);
    const int lane  = threadIdx.x & 63;
    const int b = token >> 13, p = token & 8191;

    const int slot0 = (p >> 11) * 4 + b, j0 = p & 2047;
    float d0 = g_den[slot0 * LSEG + j0];
    float sum = d0;
    int slot1 = -1, j1 = 0, slot2 = -1, j2 = 0;
    float d1 = 0.f, d2 = 0.f;
    if ((p & 1) == 0) {
        slot1 = 16 + (p >> 12) * 4 + b; j1 = (p & 4095) >> 1;
        d1 = g_den[slot1 * LSEG + j1]; sum += d1;
    }
    if ((p & 3) == 0) {
        slot2 = 24 + b; j2 = p >> 2;
        d2 = g_den[slot2 * LSEG + j2]; sum += d2;
    }
    const float inv = 1.0f / sum;
    const int c = lane << 2;

    float4 o0 = *(const float4*)(g_O + ((long)slot0 * LSEG + j0) * DD + c);
    float a0 = d0 * inv;
    float4 res;
    res.x = o0.x * a0; res.y = o0.y * a0; res.z = o0.z * a0; res.w = o0.w * a0;
    if (slot1 >= 0) {
        float4 o1 = *(const float4*)(g_O + ((long)slot1 * LSEG + j1) * DD + c);
        float a1 = d1 * inv;
        res.x = fmaf(o1.x, a1, res.x); res.y = fmaf(o1.y, a1, res.y);
        res.z = fmaf(o1.z, a1, res.z); res.w = fmaf(o1.w, a1, res.w);
    }
    if (slot2 >= 0) {
        float4 o2v = *(const float4*)(g_O + ((long)slot2 * LSEG + j2) * DD + c);
        float a2 = d2 * inv;
        res.x = fmaf(o2v.x, a2, res.x); res.y = fmaf(o2v.y, a2, res.y);
        res.z = fmaf(o2v.z, a2, res.z); res.w = fmaf(o2v.w, a2, res.w);
    }
    *(float4*)(out + ((long)b * NN + p) * DD + c) = res;
}

// ================= launch ====================================================
extern "C" void kernel_launch(void* const* d_in, const int* in_sizes, int n_in,
                              void* d_out, int out_size)
{
    (void)in_sizes; (void)n_in; (void)out_size;
    const float* x  = (const float*)d_in[0];
    const float* Wq = (const float*)d_in[1];
    const float* Wk = (const float*)d_in[2];
    const float* Wv = (const float*)d_in[3];

    cudaFuncSetAttribute(qkv_mma_kernel, cudaFuncAttributeMaxDynamicSharedMemorySize,
                         QKV_SMEM);
    cudaFuncSetAttribute(attn_kernel, cudaFuncAttributeMaxDynamicSharedMemorySize,
                         SM_TOTAL);

    split_x_kernel<<<8192, 256>>>(x);
    split_w_kernel<<<dim3(8, 8, 3), 256>>>(Wq, Wk, Wv);
    qkv_mma_kernel<<<dim3(256, 2, 3), 256, QKV_SMEM>>>();
    attn_kernel<<<dim3(32, 28), 256, SM_TOTAL>>>();
    combine_kernel<<<8192, 256>>>((float*)d_out);
}